// round 5
// baseline (speedup 1.0000x reference)
#include <cuda_runtime.h>
#include <cuda_bf16.h>
#include <math.h>
#include <stdint.h>

// Problem constants
#define BB   64
#define FF   32
#define NN   36
#define REGION 1024
#define HIDDEN 1024
#define FEAT2  3072
#define M1   (BB*FF*NN)       // 73728 rows of spatial GEMM
#define M2   (BB*FF)          // 2048 rows of temporal GEMM

// ---------------- scratch (device globals; no allocation allowed) ----------------
__device__ float g_hproj_s[BB * 1024];
__device__ float g_hproj_t[BB * 1024];
__device__ float g_score1[M1];
__device__ float g_feat[M2 * FEAT2];
__device__ float g_score2[M2];

// ================= PTX helpers =================
__device__ __forceinline__ uint32_t smem_u32(const void* p) {
    uint32_t a;
    asm("{ .reg .u64 t; cvta.to.shared.u64 t, %1; cvt.u32.u64 %0, t; }" : "=r"(a) : "l"(p));
    return a;
}

__device__ __forceinline__ void cp_async16(uint32_t dst, const void* src) {
    asm volatile("cp.async.cg.shared.global [%0], [%1], 16;" :: "r"(dst), "l"(src));
}
#define CP_COMMIT() asm volatile("cp.async.commit_group;" ::: "memory")

__device__ __forceinline__ void ldsm_x4(uint32_t r[4], uint32_t addr) {
    asm volatile("ldmatrix.sync.aligned.m8n8.x4.shared.b16 {%0,%1,%2,%3}, [%4];"
                 : "=r"(r[0]), "=r"(r[1]), "=r"(r[2]), "=r"(r[3]) : "r"(addr));
}

__device__ __forceinline__ void mma_tf32(float c[4], const uint32_t a[4], uint32_t b0, uint32_t b1) {
    asm volatile(
        "mma.sync.aligned.m16n8k8.row.col.f32.tf32.tf32.f32 "
        "{%0,%1,%2,%3}, {%4,%5,%6,%7}, {%8,%9}, {%0,%1,%2,%3};"
        : "+f"(c[0]), "+f"(c[1]), "+f"(c[2]), "+f"(c[3])
        : "r"(a[0]), "r"(a[1]), "r"(a[2]), "r"(a[3]), "r"(b0), "r"(b1));
}

// swizzled offset within a [rows x 32 float] tile (128B rows, SW128 pattern)
__device__ __forceinline__ uint32_t tile_off(int row, int chunk16) {
    return (uint32_t)(row * 128 + ((chunk16 ^ (row & 7)) << 4));
}

// ================= tf32 mma.sync fused GEMM + tanh-dot epilogue =================
// C[m,a] = sum_k A[m,k]*W[a,k]; score[m] += sum_a tanh(C[m,a]+hproj[b(m),a])*wa[a]
// CTA: 128 x NT, 256 threads = 8 warps (2 M x 4 N). Warp tile 64 x (NT/4).
// K-chunks of 32 floats, 2-stage cp.async pipeline, 2 CTAs/SM for overlap.

template <int NT>
__device__ __forceinline__ void load_stage(uint32_t base, const float* Ag, const float* Wg,
                                           int K, int tid) {
    #pragma unroll
    for (int it = 0; it < (1024 + NT * 8) / 256; it++) {
        int id = tid + it * 256;
        uint32_t dst; const float* src;
        if (id < 1024) {
            int r = id >> 3, c = id & 7;
            dst = base + tile_off(r, c);
            src = Ag + (size_t)r * K + c * 4;
        } else {
            int j = id - 1024;
            int r = j >> 3, c = j & 7;
            dst = base + 16384 + tile_off(r, c);
            src = Wg + (size_t)r * K + c * 4;
        }
        cp_async16(dst, src);
    }
}

template <int NT>
__global__ __launch_bounds__(256, 2) void gemm_score_mma(
    const float* __restrict__ A, const float* __restrict__ W,
    const float* __restrict__ hproj, const float* __restrict__ wa,
    float* __restrict__ score, int K, int rpb)
{
    constexpr int WN = NT / 4;          // warp n-extent (64 or 32)
    constexpr int MI = 4;               // 4 m-tiles of 16 -> 64 rows per warp
    constexpr int NI = WN / 8;          // n-tiles of 8 per warp
    constexpr int STAGE = 16384 + NT * 128;
    constexpr int OFF_WA = 2 * STAGE;
    constexpr int OFF_HP = OFF_WA + NT * 4;

    extern __shared__ char smem[];
    const uint32_t sb = smem_u32(smem);
    const int tid = threadIdx.x;
    const int lane = tid & 31;
    const int warp = tid >> 5;
    const int warp_m = warp >> 2;       // 0..1
    const int warp_n = warp & 3;        // 0..3
    const int m0 = blockIdx.x * 128;
    const int n0 = blockIdx.y * NT;
    const int S = K >> 5;

    // epilogue constants into smem
    {
        float* wa_s = (float*)(smem + OFF_WA);
        float* hp_s = (float*)(smem + OFF_HP);
        for (int i = tid; i < NT; i += 256) wa_s[i] = wa[n0 + i];
        int nb = 128 / rpb; if (nb < 1) nb = 1;
        int b0 = m0 / rpb;
        for (int i = tid; i < nb * NT; i += 256)
            hp_s[i] = hproj[(size_t)(b0 + i / NT) * 1024 + n0 + (i % NT)];
    }

    const float* Abase = A + (size_t)m0 * K;
    const float* Wbase = W + (size_t)n0 * K;

    float acc[MI][NI][4];
    #pragma unroll
    for (int i = 0; i < MI; i++)
        #pragma unroll
        for (int j = 0; j < NI; j++)
            #pragma unroll
            for (int q = 0; q < 4; q++) acc[i][j][q] = 0.f;

    const int lrow = lane & 15;          // row within 16-row group
    const int lhi  = lane >> 4;          // 16B chunk select within k8

    // within-tile swizzled offsets at chunk = lhi.
    // Per k8 step s: chunk = s*2 + lhi = (s*2) | lhi, and the swizzle XOR is
    // confined to bits 4..6, so addr = stage_base + (off ^ (s << 5)) is exact.
    uint32_t a_off[MI], b_off[NI / 2];
    #pragma unroll
    for (int mi = 0; mi < MI; mi++)
        a_off[mi] = tile_off(warp_m * 64 + mi * 16 + lrow, lhi);
    #pragma unroll
    for (int p = 0; p < NI / 2; p++)
        b_off[p] = 16384u + tile_off(warp_n * WN + p * 16 + lrow, lhi);

    // prologue: 2-stage pipeline
    load_stage<NT>(sb, Abase, Wbase, K, tid);                     CP_COMMIT();
    load_stage<NT>(sb + STAGE, Abase + 32, Wbase + 32, K, tid);   CP_COMMIT();

    for (int kc = 0; kc < S; kc++) {
        asm volatile("cp.async.wait_group 1;" ::: "memory");
        __syncthreads();

        const uint32_t stage_base = sb + (kc & 1) * STAGE;

        #pragma unroll
        for (int s = 0; s < 4; s++) {
            const uint32_t x = (uint32_t)s << 5;   // XOR stays in chunk-field bits 5..6
            uint32_t af[MI][4];
            #pragma unroll
            for (int mi = 0; mi < MI; mi++)
                ldsm_x4(af[mi], stage_base + (a_off[mi] ^ x));
            uint32_t bf[NI][2];
            #pragma unroll
            for (int p = 0; p < NI / 2; p++) {
                uint32_t r[4];
                ldsm_x4(r, stage_base + (b_off[p] ^ x));
                bf[2*p][0] = r[0]; bf[2*p][1] = r[2];
                bf[2*p+1][0] = r[1]; bf[2*p+1][1] = r[3];
            }
            #pragma unroll
            for (int mi = 0; mi < MI; mi++)
                #pragma unroll
                for (int ni = 0; ni < NI; ni++)
                    mma_tf32(acc[mi][ni], af[mi], bf[ni][0], bf[ni][1]);
        }
        __syncthreads();

        if (kc + 2 < S)
            load_stage<NT>(sb + (kc & 1) * STAGE,
                           Abase + (kc + 2) * 32, Wbase + (kc + 2) * 32, K, tid);
        CP_COMMIT();   // uniform commit keeps wait_group 1 exact through the tail
    }

    // ---- epilogue: tanh + weighted column reduction ----
    const float* wa_s = (const float*)(smem + OFF_WA);
    const float* hp_s = (const float*)(smem + OFF_HP);
    const int g = lane >> 2, tig = lane & 3;

    #pragma unroll
    for (int mi = 0; mi < MI; mi++) {
        int r0 = warp_m * 64 + mi * 16 + g;
        int r1 = r0 + 8;
        int bl0 = r0 / rpb, bl1 = r1 / rpb;
        const float* hp0 = hp_s + bl0 * NT;
        const float* hp1 = hp_s + bl1 * NT;
        float s0 = 0.f, s1 = 0.f;
        #pragma unroll
        for (int ni = 0; ni < NI; ni++) {
            int cl = warp_n * WN + ni * 8 + 2 * tig;
            float w0 = wa_s[cl], w1 = wa_s[cl + 1];
            float t;
            asm("tanh.approx.f32 %0, %1;" : "=f"(t) : "f"(acc[mi][ni][0] + hp0[cl]));     s0 += t * w0;
            asm("tanh.approx.f32 %0, %1;" : "=f"(t) : "f"(acc[mi][ni][1] + hp0[cl + 1])); s0 += t * w1;
            asm("tanh.approx.f32 %0, %1;" : "=f"(t) : "f"(acc[mi][ni][2] + hp1[cl]));     s1 += t * w0;
            asm("tanh.approx.f32 %0, %1;" : "=f"(t) : "f"(acc[mi][ni][3] + hp1[cl + 1])); s1 += t * w1;
        }
        s0 += __shfl_xor_sync(0xffffffffu, s0, 1);
        s0 += __shfl_xor_sync(0xffffffffu, s0, 2);
        s1 += __shfl_xor_sync(0xffffffffu, s1, 1);
        s1 += __shfl_xor_sync(0xffffffffu, s1, 2);
        if (tig == 0) {
            atomicAdd(&score[m0 + r0], s0);
            atomicAdd(&score[m0 + r1], s1);
        }
    }
}

// ================= small kernels =================
__global__ void zero_kernel(float* __restrict__ p, int n) {
    int i = blockIdx.x * blockDim.x + threadIdx.x;
    if (i < n) p[i] = 0.0f;
}

__global__ __launch_bounds__(256) void hproj_kernel(
    const float* __restrict__ hidden, const float* __restrict__ Wh,
    const float* __restrict__ bh, const float* __restrict__ bv,
    float* __restrict__ out)
{
    int b = blockIdx.x;
    int achunk = blockIdx.y;
    __shared__ float h[HIDDEN];
    for (int i = threadIdx.x; i < HIDDEN; i += 256)
        h[i] = hidden[b * HIDDEN + i];
    __syncthreads();
    int warp = threadIdx.x >> 5, lane = threadIdx.x & 31;
    for (int al = warp; al < 128; al += 8) {
        int a = achunk * 128 + al;
        const float* w = Wh + (size_t)a * HIDDEN;
        float acc = 0.f;
        #pragma unroll 8
        for (int k = lane; k < HIDDEN; k += 32) acc += w[k] * h[k];
        #pragma unroll
        for (int off = 16; off > 0; off >>= 1)
            acc += __shfl_xor_sync(0xffffffffu, acc, off);
        if (lane == 0) out[b * 1024 + a] = acc + bh[a] + bv[a];
    }
}

__global__ __launch_bounds__(256) void spatial_kernel(
    const float* __restrict__ obj, const float* __restrict__ frame,
    const float* __restrict__ score, float* __restrict__ feat)
{
    int bf = blockIdx.x;
    __shared__ float alpha[NN];
    if (threadIdx.x == 0) {
        float s[NN];
        float mx = -1e30f;
        #pragma unroll
        for (int n = 0; n < NN; n++) { s[n] = score[bf * NN + n]; mx = fmaxf(mx, s[n]); }
        float sum = 0.f;
        #pragma unroll
        for (int n = 0; n < NN; n++) { float e = expf(s[n] - mx); alpha[n] = e; sum += e; }
        float inv = 1.f / sum;
        #pragma unroll
        for (int n = 0; n < NN; n++) alpha[n] *= inv;
    }
    __syncthreads();

    const float* base = obj + (size_t)bf * NN * REGION;
    float* frow = feat + (size_t)bf * FEAT2;
    for (int d = threadIdx.x; d < REGION; d += 256) {
        float acc = 0.f;
        #pragma unroll 6
        for (int n = 0; n < NN; n++) acc += alpha[n] * base[(size_t)n * REGION + d];
        frow[d] = acc;
    }
    const float* frm = frame + (size_t)bf * (2 * HIDDEN);
    for (int d = threadIdx.x; d < 2 * HIDDEN; d += 256)
        frow[REGION + d] = frm[d];
}

__global__ __launch_bounds__(256) void temporal_kernel(
    const float* __restrict__ feat, const float* __restrict__ score2,
    float* __restrict__ out)
{
    int b = blockIdx.x;
    __shared__ float beta[FF];
    if (threadIdx.x == 0) {
        float s[FF];
        float mx = -1e30f;
        #pragma unroll
        for (int f = 0; f < FF; f++) { s[f] = score2[b * FF + f]; mx = fmaxf(mx, s[f]); }
        float sum = 0.f;
        #pragma unroll
        for (int f = 0; f < FF; f++) { float e = expf(s[f] - mx); beta[f] = e; sum += e; }
        float inv = 1.f / sum;
        #pragma unroll
        for (int f = 0; f < FF; f++) beta[f] *= inv;
    }
    __syncthreads();

    int d0 = blockIdx.y * (FEAT2 / 4);
    for (int d = d0 + threadIdx.x; d < d0 + FEAT2 / 4; d += 256) {
        float acc = 0.f;
        #pragma unroll 8
        for (int f = 0; f < FF; f++)
            acc += beta[f] * feat[((size_t)b * FF + f) * FEAT2 + d];
        out[(size_t)b * FEAT2 + d] = acc;
    }
}

// ================= launch =================
extern "C" void kernel_launch(void* const* d_in, const int* in_sizes, int n_in,
                              void* d_out, int out_size)
{
    const float* frame  = (const float*)d_in[0];
    const float* obj    = (const float*)d_in[1];
    const float* hidden = (const float*)d_in[2];
    const float* s_wh_w = (const float*)d_in[3];
    const float* s_wh_b = (const float*)d_in[4];
    const float* s_wv_w = (const float*)d_in[5];
    const float* s_wv_b = (const float*)d_in[6];
    const float* s_wa_w = (const float*)d_in[7];
    const float* t_wh_w = (const float*)d_in[8];
    const float* t_wh_b = (const float*)d_in[9];
    const float* t_wv_w = (const float*)d_in[10];
    const float* t_wv_b = (const float*)d_in[11];
    const float* t_wa_w = (const float*)d_in[12];
    float* out = (float*)d_out;

    float *p_hs, *p_ht, *p_s1, *p_feat, *p_s2;
    cudaGetSymbolAddress((void**)&p_hs, g_hproj_s);
    cudaGetSymbolAddress((void**)&p_ht, g_hproj_t);
    cudaGetSymbolAddress((void**)&p_s1, g_score1);
    cudaGetSymbolAddress((void**)&p_feat, g_feat);
    cudaGetSymbolAddress((void**)&p_s2, g_score2);

    // smem: 2*(16384 + NT*128) + NT*4 + 4*NT*4
    const int SMEM_256 = 2 * (16384 + 256 * 128) + 256 * 4 + 4 * 256 * 4;   // 103424 -> 2 CTAs/SM
    const int SMEM_128 = 2 * (16384 + 128 * 128) + 128 * 4 + 4 * 128 * 4;   //  68096 -> 3 CTAs/SM
    cudaFuncSetAttribute(gemm_score_mma<256>, cudaFuncAttributeMaxDynamicSharedMemorySize, SMEM_256);
    cudaFuncSetAttribute(gemm_score_mma<128>, cudaFuncAttributeMaxDynamicSharedMemorySize, SMEM_128);

    // hidden-state projections (fold in both biases)
    dim3 hg(BB, 8);
    hproj_kernel<<<hg, 256>>>(hidden, s_wh_w, s_wh_b, s_wv_b, p_hs);
    hproj_kernel<<<hg, 256>>>(hidden, t_wh_w, t_wh_b, t_wv_b, p_ht);

    // spatial attention scores: 155 GFLOP tf32 mma.sync GEMM, fused epilogue
    zero_kernel<<<(M1 + 255) / 256, 256>>>(p_s1, M1);
    gemm_score_mma<256><<<dim3(M1 / 128, 4), 256, SMEM_256>>>(
        obj, s_wv_w, p_hs, s_wa_w, p_s1, REGION, FF * NN);

    // softmax over boxes + weighted object sum + concat frame feats
    spatial_kernel<<<M2, 256>>>(obj, frame, p_s1, p_feat);

    // temporal attention scores (NT=128 -> 16x8 = 128 CTAs)
    zero_kernel<<<(M2 + 255) / 256, 256>>>(p_s2, M2);
    gemm_score_mma<128><<<dim3(M2 / 128, 8), 256, SMEM_128>>>(
        p_feat, t_wv_w, p_ht, t_wa_w, p_s2, FEAT2, FF);

    // softmax over frames + weighted feat sum -> [64, 3072]
    temporal_kernel<<<dim3(BB, 4), 256>>>(p_feat, p_s2, out);
}

// round 6
// speedup vs baseline: 2.3433x; 2.3433x over previous
#include <cuda_runtime.h>
#include <cuda_bf16.h>
#include <math.h>
#include <stdint.h>

// Problem constants
#define BB   64
#define FF   32
#define NN   36
#define REGION 1024
#define HIDDEN 1024
#define FEAT2  3072
#define M1   (BB*FF*NN)       // 73728 rows of spatial GEMM
#define M2   (BB*FF)          // 2048 rows of temporal GEMM

// ---------------- scratch (device globals; no allocation allowed) ----------------
__device__ float g_hproj_s[BB * 1024];
__device__ float g_hproj_t[BB * 1024];
__device__ float g_score1[M1];
__device__ float g_feat[M2 * FEAT2];
__device__ float g_score2[M2];

// ================= PTX helpers =================
__device__ __forceinline__ uint32_t smem_u32(const void* p) {
    uint32_t a;
    asm("{ .reg .u64 t; cvta.to.shared.u64 t, %1; cvt.u32.u64 %0, t; }" : "=r"(a) : "l"(p));
    return a;
}

__device__ __forceinline__ void cp_async16(uint32_t dst, const void* src) {
    asm volatile("cp.async.cg.shared.global [%0], [%1], 16;" :: "r"(dst), "l"(src));
}
#define CP_COMMIT() asm volatile("cp.async.commit_group;" ::: "memory")

__device__ __forceinline__ void ldsm_x4(uint32_t r[4], uint32_t addr) {
    asm volatile("ldmatrix.sync.aligned.m8n8.x4.shared.b16 {%0,%1,%2,%3}, [%4];"
                 : "=r"(r[0]), "=r"(r[1]), "=r"(r[2]), "=r"(r[3]) : "r"(addr));
}

__device__ __forceinline__ void mma_tf32(float c[4], const uint32_t a[4], uint32_t b0, uint32_t b1) {
    asm volatile(
        "mma.sync.aligned.m16n8k8.row.col.f32.tf32.tf32.f32 "
        "{%0,%1,%2,%3}, {%4,%5,%6,%7}, {%8,%9}, {%0,%1,%2,%3};"
        : "+f"(c[0]), "+f"(c[1]), "+f"(c[2]), "+f"(c[3])
        : "r"(a[0]), "r"(a[1]), "r"(a[2]), "r"(a[3]), "r"(b0), "r"(b1));
}

// swizzled offset within a [rows x 32 float] tile (128B rows, SW128 pattern)
__device__ __forceinline__ uint32_t tile_off(int row, int chunk16) {
    return (uint32_t)(row * 128 + ((chunk16 ^ (row & 7)) << 4));
}

// ================= tf32 mma.sync fused GEMM + tanh-dot epilogue =================
// C[m,a] = sum_k A[m,k]*W[a,k]; score[m] += sum_a tanh(C[m,a]+hproj[b(m),a])*wa[a]
// CTA: 128 x NT, 512 threads = 16 warps (4 M x 4 N). Warp tile 32 x (NT/4).
// acc = 2x(NT/32)x4 regs/thread -> no spill at 128-reg budget; 16 warps/SM.
// K-chunks of 32 floats, 3-stage cp.async pipeline.

template <int NT>
__device__ __forceinline__ void load_stage(uint32_t base, const float* Ag, const float* Wg,
                                           int K, int tid) {
    #pragma unroll
    for (int it = 0; it < (1024 + NT * 8) / 512; it++) {
        int id = tid + it * 512;
        uint32_t dst; const float* src;
        if (id < 1024) {
            int r = id >> 3, c = id & 7;
            dst = base + tile_off(r, c);
            src = Ag + (size_t)r * K + c * 4;
        } else {
            int j = id - 1024;
            int r = j >> 3, c = j & 7;
            dst = base + 16384 + tile_off(r, c);
            src = Wg + (size_t)r * K + c * 4;
        }
        cp_async16(dst, src);
    }
}

template <int NT>
__global__ __launch_bounds__(512, 1) void gemm_score_mma(
    const float* __restrict__ A, const float* __restrict__ W,
    const float* __restrict__ hproj, const float* __restrict__ wa,
    float* __restrict__ score, int K, int rpb)
{
    constexpr int WN = NT / 4;          // warp n-extent (64 or 32)
    constexpr int MI = 2;               // 2 m-tiles of 16 -> 32 rows per warp
    constexpr int NI = WN / 8;          // n-tiles of 8 per warp
    constexpr int STAGE = 16384 + NT * 128;
    constexpr int OFF_WA = 3 * STAGE;
    constexpr int OFF_HP = OFF_WA + NT * 4;

    extern __shared__ char smem[];
    const uint32_t sb = smem_u32(smem);
    const int tid = threadIdx.x;
    const int lane = tid & 31;
    const int warp = tid >> 5;
    const int warp_m = warp >> 2;       // 0..3
    const int warp_n = warp & 3;        // 0..3
    const int m0 = blockIdx.x * 128;
    const int n0 = blockIdx.y * NT;
    const int S = K >> 5;

    // epilogue constants into smem
    {
        float* wa_s = (float*)(smem + OFF_WA);
        float* hp_s = (float*)(smem + OFF_HP);
        for (int i = tid; i < NT; i += 512) wa_s[i] = wa[n0 + i];
        int nb = 128 / rpb; if (nb < 1) nb = 1;
        int b0 = m0 / rpb;
        for (int i = tid; i < nb * NT; i += 512)
            hp_s[i] = hproj[(size_t)(b0 + i / NT) * 1024 + n0 + (i % NT)];
    }

    const float* Abase = A + (size_t)m0 * K;
    const float* Wbase = W + (size_t)n0 * K;

    float acc[MI][NI][4];
    #pragma unroll
    for (int i = 0; i < MI; i++)
        #pragma unroll
        for (int j = 0; j < NI; j++)
            #pragma unroll
            for (int q = 0; q < 4; q++) acc[i][j][q] = 0.f;

    const int lrow = lane & 15;          // row within 16-row group
    const int lhi  = lane >> 4;          // 16B chunk select within k8

    // within-tile swizzled offsets at chunk = lhi; per k8 step s the chunk
    // becomes s*2+lhi = (s*2)|lhi and the swizzle XOR stays in bits 4..6,
    // so addr = stage_base + (off ^ (s << 5)) is exact.
    uint32_t a_off[MI], b_off[NI / 2];
    #pragma unroll
    for (int mi = 0; mi < MI; mi++)
        a_off[mi] = tile_off(warp_m * 32 + mi * 16 + lrow, lhi);
    #pragma unroll
    for (int p = 0; p < NI / 2; p++)
        b_off[p] = 16384u + tile_off(warp_n * WN + p * 16 + lrow, lhi);

    // prologue: fill 2 of 3 stages
    load_stage<NT>(sb, Abase, Wbase, K, tid);                     CP_COMMIT();
    load_stage<NT>(sb + STAGE, Abase + 32, Wbase + 32, K, tid);   CP_COMMIT();

    int buf = 0;
    for (int kc = 0; kc < S; kc++) {
        if (kc + 2 < S) {
            int nb3 = kc + 2;
            load_stage<NT>(sb + (nb3 % 3) * STAGE, Abase + nb3 * 32, Wbase + nb3 * 32, K, tid);
        }
        CP_COMMIT();
        asm volatile("cp.async.wait_group 2;" ::: "memory");
        __syncthreads();

        const uint32_t stage_base = sb + buf * STAGE;

        #pragma unroll
        for (int s = 0; s < 4; s++) {
            const uint32_t x = (uint32_t)s << 5;   // XOR stays in chunk-field bits 5..6
            uint32_t af[MI][4];
            #pragma unroll
            for (int mi = 0; mi < MI; mi++)
                ldsm_x4(af[mi], stage_base + (a_off[mi] ^ x));
            uint32_t bf[NI][2];
            #pragma unroll
            for (int p = 0; p < NI / 2; p++) {
                uint32_t r[4];
                ldsm_x4(r, stage_base + (b_off[p] ^ x));
                bf[2*p][0] = r[0]; bf[2*p][1] = r[2];
                bf[2*p+1][0] = r[1]; bf[2*p+1][1] = r[3];
            }
            #pragma unroll
            for (int mi = 0; mi < MI; mi++)
                #pragma unroll
                for (int ni = 0; ni < NI; ni++)
                    mma_tf32(acc[mi][ni], af[mi], bf[ni][0], bf[ni][1]);
        }
        __syncthreads();
        buf++; if (buf == 3) buf = 0;
    }

    // ---- epilogue: tanh + weighted column reduction ----
    const float* wa_s = (const float*)(smem + OFF_WA);
    const float* hp_s = (const float*)(smem + OFF_HP);
    const int g = lane >> 2, tig = lane & 3;

    #pragma unroll
    for (int mi = 0; mi < MI; mi++) {
        int r0 = warp_m * 32 + mi * 16 + g;
        int r1 = r0 + 8;
        int bl0 = r0 / rpb, bl1 = r1 / rpb;
        const float* hp0 = hp_s + bl0 * NT;
        const float* hp1 = hp_s + bl1 * NT;
        float s0 = 0.f, s1 = 0.f;
        #pragma unroll
        for (int ni = 0; ni < NI; ni++) {
            int cl = warp_n * WN + ni * 8 + 2 * tig;
            float w0 = wa_s[cl], w1 = wa_s[cl + 1];
            float t;
            asm("tanh.approx.f32 %0, %1;" : "=f"(t) : "f"(acc[mi][ni][0] + hp0[cl]));     s0 += t * w0;
            asm("tanh.approx.f32 %0, %1;" : "=f"(t) : "f"(acc[mi][ni][1] + hp0[cl + 1])); s0 += t * w1;
            asm("tanh.approx.f32 %0, %1;" : "=f"(t) : "f"(acc[mi][ni][2] + hp1[cl]));     s1 += t * w0;
            asm("tanh.approx.f32 %0, %1;" : "=f"(t) : "f"(acc[mi][ni][3] + hp1[cl + 1])); s1 += t * w1;
        }
        s0 += __shfl_xor_sync(0xffffffffu, s0, 1);
        s0 += __shfl_xor_sync(0xffffffffu, s0, 2);
        s1 += __shfl_xor_sync(0xffffffffu, s1, 1);
        s1 += __shfl_xor_sync(0xffffffffu, s1, 2);
        if (tig == 0) {
            atomicAdd(&score[m0 + r0], s0);
            atomicAdd(&score[m0 + r1], s1);
        }
    }
}

// ================= small kernels =================
__global__ void zero_kernel(float* __restrict__ p, int n) {
    int i = blockIdx.x * blockDim.x + threadIdx.x;
    if (i < n) p[i] = 0.0f;
}

__global__ __launch_bounds__(256) void hproj_kernel(
    const float* __restrict__ hidden, const float* __restrict__ Wh,
    const float* __restrict__ bh, const float* __restrict__ bv,
    float* __restrict__ out)
{
    int b = blockIdx.x;
    int achunk = blockIdx.y;
    __shared__ float h[HIDDEN];
    for (int i = threadIdx.x; i < HIDDEN; i += 256)
        h[i] = hidden[b * HIDDEN + i];
    __syncthreads();
    int warp = threadIdx.x >> 5, lane = threadIdx.x & 31;
    for (int al = warp; al < 128; al += 8) {
        int a = achunk * 128 + al;
        const float* w = Wh + (size_t)a * HIDDEN;
        float acc = 0.f;
        #pragma unroll 8
        for (int k = lane; k < HIDDEN; k += 32) acc += w[k] * h[k];
        #pragma unroll
        for (int off = 16; off > 0; off >>= 1)
            acc += __shfl_xor_sync(0xffffffffu, acc, off);
        if (lane == 0) out[b * 1024 + a] = acc + bh[a] + bv[a];
    }
}

__global__ __launch_bounds__(256) void spatial_kernel(
    const float* __restrict__ obj, const float* __restrict__ frame,
    const float* __restrict__ score, float* __restrict__ feat)
{
    int bf = blockIdx.x;
    __shared__ float alpha[NN];
    if (threadIdx.x == 0) {
        float s[NN];
        float mx = -1e30f;
        #pragma unroll
        for (int n = 0; n < NN; n++) { s[n] = score[bf * NN + n]; mx = fmaxf(mx, s[n]); }
        float sum = 0.f;
        #pragma unroll
        for (int n = 0; n < NN; n++) { float e = expf(s[n] - mx); alpha[n] = e; sum += e; }
        float inv = 1.f / sum;
        #pragma unroll
        for (int n = 0; n < NN; n++) alpha[n] *= inv;
    }
    __syncthreads();

    const float* base = obj + (size_t)bf * NN * REGION;
    float* frow = feat + (size_t)bf * FEAT2;
    for (int d = threadIdx.x; d < REGION; d += 256) {
        float acc = 0.f;
        #pragma unroll 6
        for (int n = 0; n < NN; n++) acc += alpha[n] * base[(size_t)n * REGION + d];
        frow[d] = acc;
    }
    const float* frm = frame + (size_t)bf * (2 * HIDDEN);
    for (int d = threadIdx.x; d < 2 * HIDDEN; d += 256)
        frow[REGION + d] = frm[d];
}

__global__ __launch_bounds__(256) void temporal_kernel(
    const float* __restrict__ feat, const float* __restrict__ score2,
    float* __restrict__ out)
{
    int b = blockIdx.x;
    __shared__ float beta[FF];
    if (threadIdx.x == 0) {
        float s[FF];
        float mx = -1e30f;
        #pragma unroll
        for (int f = 0; f < FF; f++) { s[f] = score2[b * FF + f]; mx = fmaxf(mx, s[f]); }
        float sum = 0.f;
        #pragma unroll
        for (int f = 0; f < FF; f++) { float e = expf(s[f] - mx); beta[f] = e; sum += e; }
        float inv = 1.f / sum;
        #pragma unroll
        for (int f = 0; f < FF; f++) beta[f] *= inv;
    }
    __syncthreads();

    int d0 = blockIdx.y * (FEAT2 / 4);
    for (int d = d0 + threadIdx.x; d < d0 + FEAT2 / 4; d += 256) {
        float acc = 0.f;
        #pragma unroll 8
        for (int f = 0; f < FF; f++)
            acc += beta[f] * feat[((size_t)b * FF + f) * FEAT2 + d];
        out[(size_t)b * FEAT2 + d] = acc;
    }
}

// ================= launch =================
extern "C" void kernel_launch(void* const* d_in, const int* in_sizes, int n_in,
                              void* d_out, int out_size)
{
    const float* frame  = (const float*)d_in[0];
    const float* obj    = (const float*)d_in[1];
    const float* hidden = (const float*)d_in[2];
    const float* s_wh_w = (const float*)d_in[3];
    const float* s_wh_b = (const float*)d_in[4];
    const float* s_wv_w = (const float*)d_in[5];
    const float* s_wv_b = (const float*)d_in[6];
    const float* s_wa_w = (const float*)d_in[7];
    const float* t_wh_w = (const float*)d_in[8];
    const float* t_wh_b = (const float*)d_in[9];
    const float* t_wv_w = (const float*)d_in[10];
    const float* t_wv_b = (const float*)d_in[11];
    const float* t_wa_w = (const float*)d_in[12];
    float* out = (float*)d_out;

    float *p_hs, *p_ht, *p_s1, *p_feat, *p_s2;
    cudaGetSymbolAddress((void**)&p_hs, g_hproj_s);
    cudaGetSymbolAddress((void**)&p_ht, g_hproj_t);
    cudaGetSymbolAddress((void**)&p_s1, g_score1);
    cudaGetSymbolAddress((void**)&p_feat, g_feat);
    cudaGetSymbolAddress((void**)&p_s2, g_score2);

    // smem: 3*(16384 + NT*128) + NT*4 + 4*NT*4
    const int SMEM_256 = 3 * (16384 + 256 * 128) + 256 * 4 + 4 * 256 * 4;   // 152576
    const int SMEM_128 = 3 * (16384 + 128 * 128) + 128 * 4 + 4 * 128 * 4;   // 100864
    cudaFuncSetAttribute(gemm_score_mma<256>, cudaFuncAttributeMaxDynamicSharedMemorySize, SMEM_256);
    cudaFuncSetAttribute(gemm_score_mma<128>, cudaFuncAttributeMaxDynamicSharedMemorySize, SMEM_128);

    // hidden-state projections (fold in both biases)
    dim3 hg(BB, 8);
    hproj_kernel<<<hg, 256>>>(hidden, s_wh_w, s_wh_b, s_wv_b, p_hs);
    hproj_kernel<<<hg, 256>>>(hidden, t_wh_w, t_wh_b, t_wv_b, p_ht);

    // spatial attention scores: 155 GFLOP tf32 mma.sync GEMM, fused epilogue
    zero_kernel<<<(M1 + 255) / 256, 256>>>(p_s1, M1);
    gemm_score_mma<256><<<dim3(M1 / 128, 4), 512, SMEM_256>>>(
        obj, s_wv_w, p_hs, s_wa_w, p_s1, REGION, FF * NN);

    // softmax over boxes + weighted object sum + concat frame feats
    spatial_kernel<<<M2, 256>>>(obj, frame, p_s1, p_feat);

    // temporal attention scores (NT=128 -> 16x8 = 128 CTAs)
    zero_kernel<<<(M2 + 255) / 256, 256>>>(p_s2, M2);
    gemm_score_mma<128><<<dim3(M2 / 128, 8), 512, SMEM_128>>>(
        p_feat, t_wv_w, p_ht, t_wa_w, p_s2, FEAT2, FF);

    // softmax over frames + weighted feat sum -> [64, 3072]
    temporal_kernel<<<dim3(BB, 4), 256>>>(p_feat, p_s2, out);
}

// round 7
// speedup vs baseline: 3.4669x; 1.4795x over previous
#include <cuda_runtime.h>
#include <cuda_fp16.h>
#include <math.h>
#include <stdint.h>

// Problem constants
#define BB   64
#define FF   32
#define NN   36
#define REGION 1024
#define HIDDEN 1024
#define FEAT2  3072
#define M1   (BB*FF*NN)       // 73728 rows of spatial GEMM
#define M2   (BB*FF)          // 2048 rows of temporal GEMM

// ---------------- scratch (device globals; no allocation allowed) ----------------
__device__ float  g_hproj_s[BB * 1024];
__device__ float  g_hproj_t[BB * 1024];
__device__ float  g_score1[M1];
__device__ float  g_feat[M2 * FEAT2];
__device__ float  g_score2[M2];
__device__ __half g_obj_h[(size_t)M1 * REGION];     // fp16 copy of object_feats
__device__ __half g_feat_h[(size_t)M2 * FEAT2];     // fp16 copy of feat
__device__ __half g_swv_h[1024 * REGION];           // fp16 s_wv_w
__device__ __half g_twv_h[1024 * FEAT2];            // fp16 t_wv_w

// ================= PTX helpers =================
__device__ __forceinline__ uint32_t smem_u32(const void* p) {
    uint32_t a;
    asm("{ .reg .u64 t; cvta.to.shared.u64 t, %1; cvt.u32.u64 %0, t; }" : "=r"(a) : "l"(p));
    return a;
}

__device__ __forceinline__ void cp_async16(uint32_t dst, const void* src) {
    asm volatile("cp.async.cg.shared.global [%0], [%1], 16;" :: "r"(dst), "l"(src));
}
#define CP_COMMIT() asm volatile("cp.async.commit_group;" ::: "memory")

__device__ __forceinline__ void ldsm_x4(uint32_t r[4], uint32_t addr) {
    asm volatile("ldmatrix.sync.aligned.m8n8.x4.shared.b16 {%0,%1,%2,%3}, [%4];"
                 : "=r"(r[0]), "=r"(r[1]), "=r"(r[2]), "=r"(r[3]) : "r"(addr));
}

__device__ __forceinline__ void mma_f16(float c[4], const uint32_t a[4], uint32_t b0, uint32_t b1) {
    asm volatile(
        "mma.sync.aligned.m16n8k16.row.col.f32.f16.f16.f32 "
        "{%0,%1,%2,%3}, {%4,%5,%6,%7}, {%8,%9}, {%0,%1,%2,%3};"
        : "+f"(c[0]), "+f"(c[1]), "+f"(c[2]), "+f"(c[3])
        : "r"(a[0]), "r"(a[1]), "r"(a[2]), "r"(a[3]), "r"(b0), "r"(b1));
}

// swizzled offset within a [rows x 64 half] tile (128B rows, SW128 pattern)
__device__ __forceinline__ uint32_t tile_off(int row, int chunk16) {
    return (uint32_t)(row * 128 + ((chunk16 ^ (row & 7)) << 4));
}

// ================= fp16 mma.sync fused GEMM + tanh-dot epilogue =================
// C[m,a] = sum_k A[m,k]*W[a,k]; score[m] += sum_a tanh(C[m,a]+hproj[b(m),a])*wa[a]
// A,W are fp16 (pre-converted), accumulate fp32. CTA: 128 x NT, 512 thr = 16 warps
// (4M x 4N), warp tile 32 x (NT/4). K-chunks of 64 halves (128B rows), 3-stage
// cp.async pipeline. Same ldmatrix addressing as tf32 version, but each s-step
// now consumes k16 via mma.m16n8k16.

template <int NT>
__device__ __forceinline__ void load_stage(uint32_t base, const __half* Ag, const __half* Wg,
                                           int K, int tid) {
    #pragma unroll
    for (int it = 0; it < (1024 + NT * 8) / 512; it++) {
        int id = tid + it * 512;
        uint32_t dst; const __half* src;
        if (id < 1024) {
            int r = id >> 3, c = id & 7;
            dst = base + tile_off(r, c);
            src = Ag + (size_t)r * K + c * 8;
        } else {
            int j = id - 1024;
            int r = j >> 3, c = j & 7;
            dst = base + 16384 + tile_off(r, c);
            src = Wg + (size_t)r * K + c * 8;
        }
        cp_async16(dst, src);
    }
}

template <int NT>
__global__ __launch_bounds__(512, 1) void gemm_score_mma(
    const __half* __restrict__ A, const __half* __restrict__ W,
    const float* __restrict__ hproj, const float* __restrict__ wa,
    float* __restrict__ score, int K, int rpb)
{
    constexpr int WN = NT / 4;          // warp n-extent (64 or 32)
    constexpr int MI = 2;               // 2 m-tiles of 16 -> 32 rows per warp
    constexpr int NI = WN / 8;          // n-tiles of 8 per warp
    constexpr int STAGE = 16384 + NT * 128;
    constexpr int OFF_WA = 3 * STAGE;
    constexpr int OFF_HP = OFF_WA + NT * 4;

    extern __shared__ char smem[];
    const uint32_t sb = smem_u32(smem);
    const int tid = threadIdx.x;
    const int lane = tid & 31;
    const int warp = tid >> 5;
    const int warp_m = warp >> 2;       // 0..3
    const int warp_n = warp & 3;        // 0..3
    const int m0 = blockIdx.x * 128;
    const int n0 = blockIdx.y * NT;
    const int S = K >> 6;               // K-chunks of 64 halves

    // epilogue constants into smem
    {
        float* wa_s = (float*)(smem + OFF_WA);
        float* hp_s = (float*)(smem + OFF_HP);
        for (int i = tid; i < NT; i += 512) wa_s[i] = wa[n0 + i];
        int nb = 128 / rpb; if (nb < 1) nb = 1;
        int b0 = m0 / rpb;
        for (int i = tid; i < nb * NT; i += 512)
            hp_s[i] = hproj[(size_t)(b0 + i / NT) * 1024 + n0 + (i % NT)];
    }

    const __half* Abase = A + (size_t)m0 * K;
    const __half* Wbase = W + (size_t)n0 * K;

    float acc[MI][NI][4];
    #pragma unroll
    for (int i = 0; i < MI; i++)
        #pragma unroll
        for (int j = 0; j < NI; j++)
            #pragma unroll
            for (int q = 0; q < 4; q++) acc[i][j][q] = 0.f;

    const int lrow = lane & 15;          // row within 16-row group
    const int lhi  = lane >> 4;          // 16B chunk (k8 half) select within k16

    // within-tile swizzled offsets at chunk = lhi; per k16 step s the chunk
    // is s*2 + lhi = (s*2)|lhi and the swizzle XOR stays in bits 4..6, so
    // addr = stage_base + (off ^ (s << 5)) is exact.
    uint32_t a_off[MI], b_off[NI / 2];
    #pragma unroll
    for (int mi = 0; mi < MI; mi++)
        a_off[mi] = tile_off(warp_m * 32 + mi * 16 + lrow, lhi);
    #pragma unroll
    for (int p = 0; p < NI / 2; p++)
        b_off[p] = 16384u + tile_off(warp_n * WN + p * 16 + lrow, lhi);

    // prologue: fill 2 of 3 stages
    load_stage<NT>(sb, Abase, Wbase, K, tid);                     CP_COMMIT();
    load_stage<NT>(sb + STAGE, Abase + 64, Wbase + 64, K, tid);   CP_COMMIT();

    int buf = 0;
    for (int kc = 0; kc < S; kc++) {
        if (kc + 2 < S) {
            int nb3 = kc + 2;
            load_stage<NT>(sb + (nb3 % 3) * STAGE, Abase + nb3 * 64, Wbase + nb3 * 64, K, tid);
        }
        CP_COMMIT();
        asm volatile("cp.async.wait_group 2;" ::: "memory");
        __syncthreads();

        const uint32_t stage_base = sb + buf * STAGE;

        #pragma unroll
        for (int s = 0; s < 4; s++) {    // 4 k16 steps per 64-half stage
            const uint32_t x = (uint32_t)s << 5;   // XOR stays in chunk-field bits 5..6
            uint32_t af[MI][4];
            #pragma unroll
            for (int mi = 0; mi < MI; mi++)
                ldsm_x4(af[mi], stage_base + (a_off[mi] ^ x));
            uint32_t bf[NI][2];
            #pragma unroll
            for (int p = 0; p < NI / 2; p++) {
                uint32_t r[4];
                ldsm_x4(r, stage_base + (b_off[p] ^ x));
                bf[2*p][0] = r[0]; bf[2*p][1] = r[2];
                bf[2*p+1][0] = r[1]; bf[2*p+1][1] = r[3];
            }
            #pragma unroll
            for (int mi = 0; mi < MI; mi++)
                #pragma unroll
                for (int ni = 0; ni < NI; ni++)
                    mma_f16(acc[mi][ni], af[mi], bf[ni][0], bf[ni][1]);
        }
        __syncthreads();
        buf++; if (buf == 3) buf = 0;
    }

    // ---- epilogue: tanh + weighted column reduction ----
    const float* wa_s = (const float*)(smem + OFF_WA);
    const float* hp_s = (const float*)(smem + OFF_HP);
    const int g = lane >> 2, tig = lane & 3;

    #pragma unroll
    for (int mi = 0; mi < MI; mi++) {
        int r0 = warp_m * 32 + mi * 16 + g;
        int r1 = r0 + 8;
        int bl0 = r0 / rpb, bl1 = r1 / rpb;
        const float* hp0 = hp_s + bl0 * NT;
        const float* hp1 = hp_s + bl1 * NT;
        float s0 = 0.f, s1 = 0.f;
        #pragma unroll
        for (int ni = 0; ni < NI; ni++) {
            int cl = warp_n * WN + ni * 8 + 2 * tig;
            float w0 = wa_s[cl], w1 = wa_s[cl + 1];
            float t;
            asm("tanh.approx.f32 %0, %1;" : "=f"(t) : "f"(acc[mi][ni][0] + hp0[cl]));     s0 += t * w0;
            asm("tanh.approx.f32 %0, %1;" : "=f"(t) : "f"(acc[mi][ni][1] + hp0[cl + 1])); s0 += t * w1;
            asm("tanh.approx.f32 %0, %1;" : "=f"(t) : "f"(acc[mi][ni][2] + hp1[cl]));     s1 += t * w0;
            asm("tanh.approx.f32 %0, %1;" : "=f"(t) : "f"(acc[mi][ni][3] + hp1[cl + 1])); s1 += t * w1;
        }
        s0 += __shfl_xor_sync(0xffffffffu, s0, 1);
        s0 += __shfl_xor_sync(0xffffffffu, s0, 2);
        s1 += __shfl_xor_sync(0xffffffffu, s1, 1);
        s1 += __shfl_xor_sync(0xffffffffu, s1, 2);
        if (tig == 0) {
            atomicAdd(&score[m0 + r0], s0);
            atomicAdd(&score[m0 + r1], s1);
        }
    }
}

// ================= small kernels =================
__global__ void zero_kernel(float* __restrict__ p, int n) {
    int i = blockIdx.x * blockDim.x + threadIdx.x;
    if (i < n) p[i] = 0.0f;
}

// vectorized f32 -> f16 conversion (n divisible by 4)
__global__ __launch_bounds__(256) void cvt_f2h(const float* __restrict__ in,
                                               __half* __restrict__ out, int n) {
    int i = (blockIdx.x * blockDim.x + threadIdx.x) * 4;
    if (i < n) {
        float4 v = *(const float4*)(in + i);
        __half2* o = (__half2*)(out + i);
        o[0] = __floats2half2_rn(v.x, v.y);
        o[1] = __floats2half2_rn(v.z, v.w);
    }
}

__global__ __launch_bounds__(256) void hproj_kernel(
    const float* __restrict__ hidden, const float* __restrict__ Wh,
    const float* __restrict__ bh, const float* __restrict__ bv,
    float* __restrict__ out)
{
    int b = blockIdx.x;
    int achunk = blockIdx.y;
    __shared__ float h[HIDDEN];
    for (int i = threadIdx.x; i < HIDDEN; i += 256)
        h[i] = hidden[b * HIDDEN + i];
    __syncthreads();
    int warp = threadIdx.x >> 5, lane = threadIdx.x & 31;
    for (int al = warp; al < 128; al += 8) {
        int a = achunk * 128 + al;
        const float* w = Wh + (size_t)a * HIDDEN;
        float acc = 0.f;
        #pragma unroll 8
        for (int k = lane; k < HIDDEN; k += 32) acc += w[k] * h[k];
        #pragma unroll
        for (int off = 16; off > 0; off >>= 1)
            acc += __shfl_xor_sync(0xffffffffu, acc, off);
        if (lane == 0) out[b * 1024 + a] = acc + bh[a] + bv[a];
    }
}

__global__ __launch_bounds__(256) void spatial_kernel(
    const float* __restrict__ obj, const float* __restrict__ frame,
    const float* __restrict__ score, float* __restrict__ feat,
    __half* __restrict__ feat_h)
{
    int bf = blockIdx.x;
    __shared__ float alpha[NN];
    if (threadIdx.x == 0) {
        float s[NN];
        float mx = -1e30f;
        #pragma unroll
        for (int n = 0; n < NN; n++) { s[n] = score[bf * NN + n]; mx = fmaxf(mx, s[n]); }
        float sum = 0.f;
        #pragma unroll
        for (int n = 0; n < NN; n++) { float e = expf(s[n] - mx); alpha[n] = e; sum += e; }
        float inv = 1.f / sum;
        #pragma unroll
        for (int n = 0; n < NN; n++) alpha[n] *= inv;
    }
    __syncthreads();

    const float* base = obj + (size_t)bf * NN * REGION;
    float* frow = feat + (size_t)bf * FEAT2;
    __half* hrow = feat_h + (size_t)bf * FEAT2;
    for (int d = threadIdx.x; d < REGION; d += 256) {
        float acc = 0.f;
        #pragma unroll 6
        for (int n = 0; n < NN; n++) acc += alpha[n] * base[(size_t)n * REGION + d];
        frow[d] = acc;
        hrow[d] = __float2half_rn(acc);
    }
    const float* frm = frame + (size_t)bf * (2 * HIDDEN);
    for (int d = threadIdx.x; d < 2 * HIDDEN; d += 256) {
        float v = frm[d];
        frow[REGION + d] = v;
        hrow[REGION + d] = __float2half_rn(v);
    }
}

__global__ __launch_bounds__(256) void temporal_kernel(
    const float* __restrict__ feat, const float* __restrict__ score2,
    float* __restrict__ out)
{
    int b = blockIdx.x;
    __shared__ float beta[FF];
    if (threadIdx.x == 0) {
        float s[FF];
        float mx = -1e30f;
        #pragma unroll
        for (int f = 0; f < FF; f++) { s[f] = score2[b * FF + f]; mx = fmaxf(mx, s[f]); }
        float sum = 0.f;
        #pragma unroll
        for (int f = 0; f < FF; f++) { float e = expf(s[f] - mx); beta[f] = e; sum += e; }
        float inv = 1.f / sum;
        #pragma unroll
        for (int f = 0; f < FF; f++) beta[f] *= inv;
    }
    __syncthreads();

    int d0 = blockIdx.y * (FEAT2 / 4);
    for (int d = d0 + threadIdx.x; d < d0 + FEAT2 / 4; d += 256) {
        float acc = 0.f;
        #pragma unroll 8
        for (int f = 0; f < FF; f++)
            acc += beta[f] * feat[((size_t)b * FF + f) * FEAT2 + d];
        out[(size_t)b * FEAT2 + d] = acc;
    }
}

// ================= launch =================
extern "C" void kernel_launch(void* const* d_in, const int* in_sizes, int n_in,
                              void* d_out, int out_size)
{
    const float* frame  = (const float*)d_in[0];
    const float* obj    = (const float*)d_in[1];
    const float* hidden = (const float*)d_in[2];
    const float* s_wh_w = (const float*)d_in[3];
    const float* s_wh_b = (const float*)d_in[4];
    const float* s_wv_w = (const float*)d_in[5];
    const float* s_wv_b = (const float*)d_in[6];
    const float* s_wa_w = (const float*)d_in[7];
    const float* t_wh_w = (const float*)d_in[8];
    const float* t_wh_b = (const float*)d_in[9];
    const float* t_wv_w = (const float*)d_in[10];
    const float* t_wv_b = (const float*)d_in[11];
    const float* t_wa_w = (const float*)d_in[12];
    float* out = (float*)d_out;

    float *p_hs, *p_ht, *p_s1, *p_feat, *p_s2;
    __half *p_obj_h, *p_feat_h, *p_swv_h, *p_twv_h;
    cudaGetSymbolAddress((void**)&p_hs, g_hproj_s);
    cudaGetSymbolAddress((void**)&p_ht, g_hproj_t);
    cudaGetSymbolAddress((void**)&p_s1, g_score1);
    cudaGetSymbolAddress((void**)&p_feat, g_feat);
    cudaGetSymbolAddress((void**)&p_s2, g_score2);
    cudaGetSymbolAddress((void**)&p_obj_h, g_obj_h);
    cudaGetSymbolAddress((void**)&p_feat_h, g_feat_h);
    cudaGetSymbolAddress((void**)&p_swv_h, g_swv_h);
    cudaGetSymbolAddress((void**)&p_twv_h, g_twv_h);

    // smem: 3*(16384 + NT*128) + NT*4 + 4*NT*4
    const int SMEM_256 = 3 * (16384 + 256 * 128) + 256 * 4 + 4 * 256 * 4;   // 152576
    const int SMEM_128 = 3 * (16384 + 128 * 128) + 128 * 4 + 4 * 128 * 4;   // 100864
    cudaFuncSetAttribute(gemm_score_mma<256>, cudaFuncAttributeMaxDynamicSharedMemorySize, SMEM_256);
    cudaFuncSetAttribute(gemm_score_mma<128>, cudaFuncAttributeMaxDynamicSharedMemorySize, SMEM_128);

    // fp16 conversions (independent of hproj; overlap on stream)
    {
        int n_obj = M1 * REGION;
        cvt_f2h<<<(n_obj / 4 + 255) / 256, 256>>>(obj, p_obj_h, n_obj);
        int n_swv = 1024 * REGION;
        cvt_f2h<<<(n_swv / 4 + 255) / 256, 256>>>(s_wv_w, p_swv_h, n_swv);
        int n_twv = 1024 * FEAT2;
        cvt_f2h<<<(n_twv / 4 + 255) / 256, 256>>>(t_wv_w, p_twv_h, n_twv);
    }

    // hidden-state projections (fold in both biases)
    dim3 hg(BB, 8);
    hproj_kernel<<<hg, 256>>>(hidden, s_wh_w, s_wh_b, s_wv_b, p_hs);
    hproj_kernel<<<hg, 256>>>(hidden, t_wh_w, t_wh_b, t_wv_b, p_ht);

    // spatial attention scores: 155 GFLOP fp16 mma.sync GEMM, fused epilogue
    zero_kernel<<<(M1 + 255) / 256, 256>>>(p_s1, M1);
    gemm_score_mma<256><<<dim3(M1 / 128, 4), 512, SMEM_256>>>(
        p_obj_h, p_swv_h, p_hs, s_wa_w, p_s1, REGION, FF * NN);

    // softmax over boxes + weighted object sum + concat frame feats (f32 + f16)
    spatial_kernel<<<M2, 256>>>(obj, frame, p_s1, p_feat, p_feat_h);

    // temporal attention scores (NT=128 -> 16x8 = 128 CTAs)
    zero_kernel<<<(M2 + 255) / 256, 256>>>(p_s2, M2);
    gemm_score_mma<128><<<dim3(M2 / 128, 8), 512, SMEM_128>>>(
        p_feat_h, p_twv_h, p_ht, t_wa_w, p_s2, FEAT2, FF);

    // softmax over frames + weighted feat sum -> [64, 3072]
    temporal_kernel<<<dim3(BB, 4), 256>>>(p_feat, p_s2, out);
}

// round 8
// speedup vs baseline: 3.6774x; 1.0607x over previous
#include <cuda_runtime.h>
#include <cuda_fp16.h>
#include <math.h>
#include <stdint.h>

// Problem constants
#define BB   64
#define FF   32
#define NN   36
#define REGION 1024
#define HIDDEN 1024
#define FEAT2  3072
#define M1   (BB*FF*NN)       // 73728 rows of spatial GEMM
#define M2   (BB*FF)          // 2048 rows of temporal GEMM

// ---------------- scratch (device globals; no allocation allowed) ----------------
__device__ float  g_hproj_s[BB * 1024];
__device__ float  g_hproj_t[BB * 1024];
__device__ float  g_score1[M1];
__device__ float  g_feat[M2 * FEAT2];
__device__ float  g_score2[M2];
__device__ __half g_obj_h[(size_t)M1 * REGION];     // fp16 copy of object_feats
__device__ __half g_feat_h[(size_t)M2 * FEAT2];     // fp16 copy of feat
__device__ __half g_swv_h[1024 * REGION];           // fp16 s_wv_w
__device__ __half g_twv_h[1024 * FEAT2];            // fp16 t_wv_w

// ================= PTX helpers =================
__device__ __forceinline__ uint32_t smem_u32(const void* p) {
    uint32_t a;
    asm("{ .reg .u64 t; cvta.to.shared.u64 t, %1; cvt.u32.u64 %0, t; }" : "=r"(a) : "l"(p));
    return a;
}

__device__ __forceinline__ void cp_async16(uint32_t dst, const void* src) {
    asm volatile("cp.async.cg.shared.global [%0], [%1], 16;" :: "r"(dst), "l"(src));
}
#define CP_COMMIT() asm volatile("cp.async.commit_group;" ::: "memory")

__device__ __forceinline__ void ldsm_x4(uint32_t r[4], uint32_t addr) {
    asm volatile("ldmatrix.sync.aligned.m8n8.x4.shared.b16 {%0,%1,%2,%3}, [%4];"
                 : "=r"(r[0]), "=r"(r[1]), "=r"(r[2]), "=r"(r[3]) : "r"(addr));
}

__device__ __forceinline__ void mma_f16(float c[4], const uint32_t a[4], uint32_t b0, uint32_t b1) {
    asm volatile(
        "mma.sync.aligned.m16n8k16.row.col.f32.f16.f16.f32 "
        "{%0,%1,%2,%3}, {%4,%5,%6,%7}, {%8,%9}, {%0,%1,%2,%3};"
        : "+f"(c[0]), "+f"(c[1]), "+f"(c[2]), "+f"(c[3])
        : "r"(a[0]), "r"(a[1]), "r"(a[2]), "r"(a[3]), "r"(b0), "r"(b1));
}

// swizzled offset within a [rows x 64 half] tile (128B rows, SW128 pattern)
__device__ __forceinline__ uint32_t tile_off(int row, int chunk16) {
    return (uint32_t)(row * 128 + ((chunk16 ^ (row & 7)) << 4));
}

// ================= fp16 mma.sync fused GEMM + tanh-dot epilogue =================
// C[m,a] = sum_k A[m,k]*W[a,k]; score[m] += sum_a tanh(C[m,a]+hproj[b(m),a])*wa[a]
// A,W fp16, fp32 accumulate. CTA: 128 x NT, 512 thr = 16 warps (4M x 4N),
// warp tile 32 x (NT/4). K-chunks of 64 halves, 3-stage cp.async pipeline.

template <int NT>
__device__ __forceinline__ void load_stage(uint32_t base, const __half* Ag, const __half* Wg,
                                           int K, int tid) {
    #pragma unroll
    for (int it = 0; it < (1024 + NT * 8) / 512; it++) {
        int id = tid + it * 512;
        uint32_t dst; const __half* src;
        if (id < 1024) {
            int r = id >> 3, c = id & 7;
            dst = base + tile_off(r, c);
            src = Ag + (size_t)r * K + c * 8;
        } else {
            int j = id - 1024;
            int r = j >> 3, c = j & 7;
            dst = base + 16384 + tile_off(r, c);
            src = Wg + (size_t)r * K + c * 8;
        }
        cp_async16(dst, src);
    }
}

template <int NT>
__global__ __launch_bounds__(512, 1) void gemm_score_mma(
    const __half* __restrict__ A, const __half* __restrict__ W,
    const float* __restrict__ hproj, const float* __restrict__ wa,
    float* __restrict__ score, int K, int rpb)
{
    constexpr int WN = NT / 4;
    constexpr int MI = 2;
    constexpr int NI = WN / 8;
    constexpr int STAGE = 16384 + NT * 128;
    constexpr int OFF_WA = 3 * STAGE;
    constexpr int OFF_HP = OFF_WA + NT * 4;

    extern __shared__ char smem[];
    const uint32_t sb = smem_u32(smem);
    const int tid = threadIdx.x;
    const int lane = tid & 31;
    const int warp = tid >> 5;
    const int warp_m = warp >> 2;
    const int warp_n = warp & 3;
    const int m0 = blockIdx.x * 128;
    const int n0 = blockIdx.y * NT;
    const int S = K >> 6;

    {
        float* wa_s = (float*)(smem + OFF_WA);
        float* hp_s = (float*)(smem + OFF_HP);
        for (int i = tid; i < NT; i += 512) wa_s[i] = wa[n0 + i];
        int nb = 128 / rpb; if (nb < 1) nb = 1;
        int b0 = m0 / rpb;
        for (int i = tid; i < nb * NT; i += 512)
            hp_s[i] = hproj[(size_t)(b0 + i / NT) * 1024 + n0 + (i % NT)];
    }

    const __half* Abase = A + (size_t)m0 * K;
    const __half* Wbase = W + (size_t)n0 * K;

    float acc[MI][NI][4];
    #pragma unroll
    for (int i = 0; i < MI; i++)
        #pragma unroll
        for (int j = 0; j < NI; j++)
            #pragma unroll
            for (int q = 0; q < 4; q++) acc[i][j][q] = 0.f;

    const int lrow = lane & 15;
    const int lhi  = lane >> 4;

    uint32_t a_off[MI], b_off[NI / 2];
    #pragma unroll
    for (int mi = 0; mi < MI; mi++)
        a_off[mi] = tile_off(warp_m * 32 + mi * 16 + lrow, lhi);
    #pragma unroll
    for (int p = 0; p < NI / 2; p++)
        b_off[p] = 16384u + tile_off(warp_n * WN + p * 16 + lrow, lhi);

    load_stage<NT>(sb, Abase, Wbase, K, tid);                     CP_COMMIT();
    load_stage<NT>(sb + STAGE, Abase + 64, Wbase + 64, K, tid);   CP_COMMIT();

    int buf = 0;
    for (int kc = 0; kc < S; kc++) {
        if (kc + 2 < S) {
            int nb3 = kc + 2;
            load_stage<NT>(sb + (nb3 % 3) * STAGE, Abase + nb3 * 64, Wbase + nb3 * 64, K, tid);
        }
        CP_COMMIT();
        asm volatile("cp.async.wait_group 2;" ::: "memory");
        __syncthreads();

        const uint32_t stage_base = sb + buf * STAGE;

        #pragma unroll
        for (int s = 0; s < 4; s++) {
            const uint32_t x = (uint32_t)s << 5;
            uint32_t af[MI][4];
            #pragma unroll
            for (int mi = 0; mi < MI; mi++)
                ldsm_x4(af[mi], stage_base + (a_off[mi] ^ x));
            uint32_t bf[NI][2];
            #pragma unroll
            for (int p = 0; p < NI / 2; p++) {
                uint32_t r[4];
                ldsm_x4(r, stage_base + (b_off[p] ^ x));
                bf[2*p][0] = r[0]; bf[2*p][1] = r[2];
                bf[2*p+1][0] = r[1]; bf[2*p+1][1] = r[3];
            }
            #pragma unroll
            for (int mi = 0; mi < MI; mi++)
                #pragma unroll
                for (int ni = 0; ni < NI; ni++)
                    mma_f16(acc[mi][ni], af[mi], bf[ni][0], bf[ni][1]);
        }
        __syncthreads();
        buf++; if (buf == 3) buf = 0;
    }

    // ---- epilogue: tanh + weighted column reduction ----
    const float* wa_s = (const float*)(smem + OFF_WA);
    const float* hp_s = (const float*)(smem + OFF_HP);
    const int g = lane >> 2, tig = lane & 3;

    #pragma unroll
    for (int mi = 0; mi < MI; mi++) {
        int r0 = warp_m * 32 + mi * 16 + g;
        int r1 = r0 + 8;
        int bl0 = r0 / rpb, bl1 = r1 / rpb;
        const float* hp0 = hp_s + bl0 * NT;
        const float* hp1 = hp_s + bl1 * NT;
        float s0 = 0.f, s1 = 0.f;
        #pragma unroll
        for (int ni = 0; ni < NI; ni++) {
            int cl = warp_n * WN + ni * 8 + 2 * tig;
            float w0 = wa_s[cl], w1 = wa_s[cl + 1];
            float t;
            asm("tanh.approx.f32 %0, %1;" : "=f"(t) : "f"(acc[mi][ni][0] + hp0[cl]));     s0 += t * w0;
            asm("tanh.approx.f32 %0, %1;" : "=f"(t) : "f"(acc[mi][ni][1] + hp0[cl + 1])); s0 += t * w1;
            asm("tanh.approx.f32 %0, %1;" : "=f"(t) : "f"(acc[mi][ni][2] + hp1[cl]));     s1 += t * w0;
            asm("tanh.approx.f32 %0, %1;" : "=f"(t) : "f"(acc[mi][ni][3] + hp1[cl + 1])); s1 += t * w1;
        }
        s0 += __shfl_xor_sync(0xffffffffu, s0, 1);
        s0 += __shfl_xor_sync(0xffffffffu, s0, 2);
        s1 += __shfl_xor_sync(0xffffffffu, s1, 1);
        s1 += __shfl_xor_sync(0xffffffffu, s1, 2);
        if (tig == 0) {
            atomicAdd(&score[m0 + r0], s0);
            atomicAdd(&score[m0 + r1], s1);
        }
    }
}

// ================= small kernels =================
__global__ void zero_kernel(float* __restrict__ p, int n) {
    int i = blockIdx.x * blockDim.x + threadIdx.x;
    if (i < n) p[i] = 0.0f;
}

// vectorized f32 -> f16 conversion (n divisible by 4)
__global__ __launch_bounds__(256) void cvt_f2h(const float* __restrict__ in,
                                               __half* __restrict__ out, int n) {
    int i = (blockIdx.x * blockDim.x + threadIdx.x) * 4;
    if (i < n) {
        float4 v = *(const float4*)(in + i);
        __half2* o = (__half2*)(out + i);
        o[0] = __floats2half2_rn(v.x, v.y);
        o[1] = __floats2half2_rn(v.z, v.w);
    }
}

// both hidden-state projections in one launch; float4 loads, 2 rows per warp iter
__global__ __launch_bounds__(256) void hproj2_kernel(
    const float* __restrict__ hidden,
    const float* __restrict__ Wh_s, const float* __restrict__ bh_s,
    const float* __restrict__ bv_s, float* __restrict__ out_s,
    const float* __restrict__ Wh_t, const float* __restrict__ bh_t,
    const float* __restrict__ bv_t, float* __restrict__ out_t)
{
    const int b = blockIdx.x;
    const int achunk = blockIdx.y;
    const int mat = blockIdx.z;
    const float* Wh = mat ? Wh_t : Wh_s;
    const float* bh = mat ? bh_t : bh_s;
    const float* bv = mat ? bv_t : bv_s;
    float* out = mat ? out_t : out_s;

    __shared__ float4 h4[256];
    for (int i = threadIdx.x; i < 256; i += 256)
        h4[i] = ((const float4*)(hidden + (size_t)b * HIDDEN))[i];
    __syncthreads();

    const int warp = threadIdx.x >> 5, lane = threadIdx.x & 31;
    for (int al = warp * 2; al < 128; al += 16) {
        int a0 = achunk * 128 + al;
        int a1 = a0 + 1;
        const float4* w0 = (const float4*)(Wh + (size_t)a0 * HIDDEN);
        const float4* w1 = (const float4*)(Wh + (size_t)a1 * HIDDEN);
        float4 c0 = {0,0,0,0}, c1 = {0,0,0,0};
        #pragma unroll
        for (int i = 0; i < 8; i++) {
            int idx = lane + i * 32;
            float4 hv = h4[idx];
            float4 x0 = w0[idx], x1 = w1[idx];
            c0.x += x0.x * hv.x; c0.y += x0.y * hv.y; c0.z += x0.z * hv.z; c0.w += x0.w * hv.w;
            c1.x += x1.x * hv.x; c1.y += x1.y * hv.y; c1.z += x1.z * hv.z; c1.w += x1.w * hv.w;
        }
        float s0 = (c0.x + c0.y) + (c0.z + c0.w);
        float s1 = (c1.x + c1.y) + (c1.z + c1.w);
        #pragma unroll
        for (int off = 16; off > 0; off >>= 1) {
            s0 += __shfl_xor_sync(0xffffffffu, s0, off);
            s1 += __shfl_xor_sync(0xffffffffu, s1, off);
        }
        if (lane == 0) {
            out[b * 1024 + a0] = s0 + bh[a0] + bv[a0];
            out[b * 1024 + a1] = s1 + bh[a1] + bv[a1];
        }
    }
}

// spatial softmax + weighted object sum (fp16 obj read) + concat
__global__ __launch_bounds__(256) void spatial_kernel(
    const __half* __restrict__ obj_h, const float* __restrict__ frame,
    const float* __restrict__ score, float* __restrict__ feat,
    __half* __restrict__ feat_h)
{
    int bf = blockIdx.x;
    __shared__ float alpha[NN];
    if (threadIdx.x == 0) {
        float s[NN];
        float mx = -1e30f;
        #pragma unroll
        for (int n = 0; n < NN; n++) { s[n] = score[bf * NN + n]; mx = fmaxf(mx, s[n]); }
        float sum = 0.f;
        #pragma unroll
        for (int n = 0; n < NN; n++) { float e = expf(s[n] - mx); alpha[n] = e; sum += e; }
        float inv = 1.f / sum;
        #pragma unroll
        for (int n = 0; n < NN; n++) alpha[n] *= inv;
    }
    __syncthreads();

    const __half2* base = (const __half2*)(obj_h + (size_t)bf * NN * REGION);
    float* frow = feat + (size_t)bf * FEAT2;
    __half2* hrow2 = (__half2*)(feat_h + (size_t)bf * FEAT2);
    for (int d2 = threadIdx.x; d2 < REGION / 2; d2 += 256) {
        float ax = 0.f, ay = 0.f;
        #pragma unroll 6
        for (int n = 0; n < NN; n++) {
            float2 v = __half22float2(base[n * (REGION / 2) + d2]);
            ax += alpha[n] * v.x;
            ay += alpha[n] * v.y;
        }
        frow[2 * d2] = ax;
        frow[2 * d2 + 1] = ay;
        hrow2[d2] = __floats2half2_rn(ax, ay);
    }
    const float* frm = frame + (size_t)bf * (2 * HIDDEN);
    for (int d = threadIdx.x; d < 2 * HIDDEN; d += 256) {
        float v = frm[d];
        frow[REGION + d] = v;
        feat_h[(size_t)bf * FEAT2 + REGION + d] = __float2half_rn(v);
    }
}

__global__ __launch_bounds__(256) void temporal_kernel(
    const float* __restrict__ feat, const float* __restrict__ score2,
    float* __restrict__ out)
{
    int b = blockIdx.x;
    __shared__ float beta[FF];
    if (threadIdx.x == 0) {
        float s[FF];
        float mx = -1e30f;
        #pragma unroll
        for (int f = 0; f < FF; f++) { s[f] = score2[b * FF + f]; mx = fmaxf(mx, s[f]); }
        float sum = 0.f;
        #pragma unroll
        for (int f = 0; f < FF; f++) { float e = expf(s[f] - mx); beta[f] = e; sum += e; }
        float inv = 1.f / sum;
        #pragma unroll
        for (int f = 0; f < FF; f++) beta[f] *= inv;
    }
    __syncthreads();

    int d0 = blockIdx.y * (FEAT2 / 4);
    for (int d = d0 + threadIdx.x; d < d0 + FEAT2 / 4; d += 256) {
        float acc = 0.f;
        #pragma unroll 8
        for (int f = 0; f < FF; f++)
            acc += beta[f] * feat[((size_t)b * FF + f) * FEAT2 + d];
        out[(size_t)b * FEAT2 + d] = acc;
    }
}

// ================= launch =================
extern "C" void kernel_launch(void* const* d_in, const int* in_sizes, int n_in,
                              void* d_out, int out_size)
{
    const float* frame  = (const float*)d_in[0];
    const float* obj    = (const float*)d_in[1];
    const float* hidden = (const float*)d_in[2];
    const float* s_wh_w = (const float*)d_in[3];
    const float* s_wh_b = (const float*)d_in[4];
    const float* s_wv_w = (const float*)d_in[5];
    const float* s_wv_b = (const float*)d_in[6];
    const float* s_wa_w = (const float*)d_in[7];
    const float* t_wh_w = (const float*)d_in[8];
    const float* t_wh_b = (const float*)d_in[9];
    const float* t_wv_w = (const float*)d_in[10];
    const float* t_wv_b = (const float*)d_in[11];
    const float* t_wa_w = (const float*)d_in[12];
    float* out = (float*)d_out;

    float *p_hs, *p_ht, *p_s1, *p_feat, *p_s2;
    __half *p_obj_h, *p_feat_h, *p_swv_h, *p_twv_h;
    cudaGetSymbolAddress((void**)&p_hs, g_hproj_s);
    cudaGetSymbolAddress((void**)&p_ht, g_hproj_t);
    cudaGetSymbolAddress((void**)&p_s1, g_score1);
    cudaGetSymbolAddress((void**)&p_feat, g_feat);
    cudaGetSymbolAddress((void**)&p_s2, g_score2);
    cudaGetSymbolAddress((void**)&p_obj_h, g_obj_h);
    cudaGetSymbolAddress((void**)&p_feat_h, g_feat_h);
    cudaGetSymbolAddress((void**)&p_swv_h, g_swv_h);
    cudaGetSymbolAddress((void**)&p_twv_h, g_twv_h);

    const int SMEM_256 = 3 * (16384 + 256 * 128) + 256 * 4 + 4 * 256 * 4;   // 152576
    const int SMEM_128 = 3 * (16384 + 128 * 128) + 128 * 4 + 4 * 128 * 4;   // 100864
    cudaFuncSetAttribute(gemm_score_mma<256>, cudaFuncAttributeMaxDynamicSharedMemorySize, SMEM_256);
    cudaFuncSetAttribute(gemm_score_mma<128>, cudaFuncAttributeMaxDynamicSharedMemorySize, SMEM_128);

    // fp16 conversions
    {
        int n_obj = M1 * REGION;
        cvt_f2h<<<(n_obj / 4 + 255) / 256, 256>>>(obj, p_obj_h, n_obj);
        int n_swv = 1024 * REGION;
        cvt_f2h<<<(n_swv / 4 + 255) / 256, 256>>>(s_wv_w, p_swv_h, n_swv);
        int n_twv = 1024 * FEAT2;
        cvt_f2h<<<(n_twv / 4 + 255) / 256, 256>>>(t_wv_w, p_twv_h, n_twv);
    }

    // hidden-state projections, both matrices in one launch
    hproj2_kernel<<<dim3(BB, 8, 2), 256>>>(hidden,
                                           s_wh_w, s_wh_b, s_wv_b, p_hs,
                                           t_wh_w, t_wh_b, t_wv_b, p_ht);

    // spatial attention scores: 155 GFLOP fp16 mma.sync GEMM, fused epilogue
    zero_kernel<<<(M1 + 255) / 256, 256>>>(p_s1, M1);
    gemm_score_mma<256><<<dim3(M1 / 128, 4), 512, SMEM_256>>>(
        p_obj_h, p_swv_h, p_hs, s_wa_w, p_s1, REGION, FF * NN);

    // softmax over boxes + weighted object sum (fp16 obj) + concat frame feats
    spatial_kernel<<<M2, 256>>>(p_obj_h, frame, p_s1, p_feat, p_feat_h);

    // temporal attention scores
    zero_kernel<<<(M2 + 255) / 256, 256>>>(p_s2, M2);
    gemm_score_mma<128><<<dim3(M2 / 128, 8), 512, SMEM_128>>>(
        p_feat_h, p_twv_h, p_ht, t_wa_w, p_s2, FEAT2, FF);

    // softmax over frames + weighted feat sum -> [64, 3072]
    temporal_kernel<<<dim3(BB, 4), 256>>>(p_feat, p_s2, out);
}

// round 9
// speedup vs baseline: 4.1078x; 1.1170x over previous
#include <cuda_runtime.h>
#include <cuda_fp16.h>
#include <math.h>
#include <stdint.h>

// Problem constants
#define BB   64
#define FF   32
#define NN   36
#define REGION 1024
#define HIDDEN 1024
#define FEAT2  3072
#define M1   (BB*FF*NN)       // 73728 rows of spatial GEMM
#define M2   (BB*FF)          // 2048 rows of temporal GEMM

// ---------------- scratch (device globals; no allocation allowed) ----------------
__device__ float  g_hproj_s[BB * 1024];
__device__ float  g_hproj_t[BB * 1024];
__device__ float  g_score1[M1];
__device__ float  g_feat[M2 * FEAT2];
__device__ float  g_score2[M2];
__device__ __half g_obj_h[(size_t)M1 * REGION];     // fp16 object_feats
__device__ __half g_feat_h[(size_t)M2 * FEAT2];     // fp16 feat
__device__ __half g_swv_h[1024 * REGION];           // fp16 s_wv_w
__device__ __half g_twv_h[1024 * FEAT2];            // fp16 t_wv_w
__device__ __half g_swh_h[1024 * HIDDEN];           // fp16 s_wh_w
__device__ __half g_twh_h[1024 * HIDDEN];           // fp16 t_wh_w
__device__ __half g_hid_h[128 * HIDDEN];            // fp16 hidden, padded to 128 rows

// ================= PTX helpers =================
__device__ __forceinline__ uint32_t smem_u32(const void* p) {
    uint32_t a;
    asm("{ .reg .u64 t; cvta.to.shared.u64 t, %1; cvt.u32.u64 %0, t; }" : "=r"(a) : "l"(p));
    return a;
}

__device__ __forceinline__ void cp_async16(uint32_t dst, const void* src) {
    asm volatile("cp.async.cg.shared.global [%0], [%1], 16;" :: "r"(dst), "l"(src));
}
#define CP_COMMIT() asm volatile("cp.async.commit_group;" ::: "memory")

__device__ __forceinline__ void ldsm_x4(uint32_t r[4], uint32_t addr) {
    asm volatile("ldmatrix.sync.aligned.m8n8.x4.shared.b16 {%0,%1,%2,%3}, [%4];"
                 : "=r"(r[0]), "=r"(r[1]), "=r"(r[2]), "=r"(r[3]) : "r"(addr));
}

__device__ __forceinline__ void mma_f16(float c[4], const uint32_t a[4], uint32_t b0, uint32_t b1) {
    asm volatile(
        "mma.sync.aligned.m16n8k16.row.col.f32.f16.f16.f32 "
        "{%0,%1,%2,%3}, {%4,%5,%6,%7}, {%8,%9}, {%0,%1,%2,%3};"
        : "+f"(c[0]), "+f"(c[1]), "+f"(c[2]), "+f"(c[3])
        : "r"(a[0]), "r"(a[1]), "r"(a[2]), "r"(a[3]), "r"(b0), "r"(b1));
}

// swizzled offset within a [rows x 64 half] tile (128B rows, SW128 pattern)
__device__ __forceinline__ uint32_t tile_off(int row, int chunk16) {
    return (uint32_t)(row * 128 + ((chunk16 ^ (row & 7)) << 4));
}

// per-stage tile loader: A 128 rows x 64 halves + B NT rows x 64 halves
template <int NT>
__device__ __forceinline__ void load_stage(uint32_t base, const __half* Ag, const __half* Wg,
                                           int K, int tid) {
    #pragma unroll
    for (int it = 0; it < (1024 + NT * 8) / 512; it++) {
        int id = tid + it * 512;
        uint32_t dst; const __half* src;
        if (id < 1024) {
            int r = id >> 3, c = id & 7;
            dst = base + tile_off(r, c);
            src = Ag + (size_t)r * K + c * 8;
        } else {
            int j = id - 1024;
            int r = j >> 3, c = j & 7;
            dst = base + 16384 + tile_off(r, c);
            src = Wg + (size_t)r * K + c * 8;
        }
        cp_async16(dst, src);
    }
}

// ======== fp16 mma GEMM mainloop (4-stage, single sync per K-chunk) ========
// Produces acc[2][NI][4] for warp tile 32 x (NT/4). Shared by both kernels.
#define GEMM_MAINLOOP(NT, NI, Abase, Wbase, K)                                        \
    const int S = (K) >> 6;                                                            \
    constexpr int STAGE = 16384 + (NT) * 128;                                          \
    load_stage<NT>(sb + 0 * STAGE, (Abase) +   0, (Wbase) +   0, (K), tid); CP_COMMIT();\
    load_stage<NT>(sb + 1 * STAGE, (Abase) +  64, (Wbase) +  64, (K), tid); CP_COMMIT();\
    load_stage<NT>(sb + 2 * STAGE, (Abase) + 128, (Wbase) + 128, (K), tid); CP_COMMIT();\
    for (int kc = 0; kc < S; kc++) {                                                   \
        if (kc + 3 < S)                                                                \
            load_stage<NT>(sb + ((kc + 3) & 3) * STAGE,                                \
                           (Abase) + (kc + 3) * 64, (Wbase) + (kc + 3) * 64, (K), tid);\
        CP_COMMIT();                                                                   \
        asm volatile("cp.async.wait_group 3;" ::: "memory");                           \
        __syncthreads();                                                               \
        const uint32_t stage_base = sb + (kc & 3) * STAGE;                             \
        _Pragma("unroll")                                                              \
        for (int s = 0; s < 4; s++) {                                                  \
            const uint32_t x = (uint32_t)s << 5;                                       \
            uint32_t af[2][4];                                                         \
            _Pragma("unroll")                                                          \
            for (int mi = 0; mi < 2; mi++)                                             \
                ldsm_x4(af[mi], stage_base + (a_off[mi] ^ x));                         \
            uint32_t bf[NI][2];                                                        \
            _Pragma("unroll")                                                          \
            for (int p = 0; p < (NI) / 2; p++) {                                       \
                uint32_t r[4];                                                         \
                ldsm_x4(r, stage_base + (b_off[p] ^ x));                               \
                bf[2*p][0] = r[0]; bf[2*p][1] = r[2];                                  \
                bf[2*p+1][0] = r[1]; bf[2*p+1][1] = r[3];                              \
            }                                                                          \
            _Pragma("unroll")                                                          \
            for (int mi = 0; mi < 2; mi++)                                             \
                _Pragma("unroll")                                                      \
                for (int ni = 0; ni < (NI); ni++)                                      \
                    mma_f16(acc[mi][ni], af[mi], bf[ni][0], bf[ni][1]);                \
        }                                                                              \
    }

// ================= GEMM + tanh-dot epilogue =================
template <int NT>
__global__ __launch_bounds__(512, 1) void gemm_score_mma(
    const __half* __restrict__ A, const __half* __restrict__ W,
    const float* __restrict__ hproj, const float* __restrict__ wa,
    float* __restrict__ score, int K, int rpb)
{
    constexpr int WN = NT / 4;
    constexpr int NI = WN / 8;
    constexpr int OFF_WA = 4 * (16384 + NT * 128);
    constexpr int OFF_HP = OFF_WA + NT * 4;

    extern __shared__ char smem[];
    const uint32_t sb = smem_u32(smem);
    const int tid = threadIdx.x;
    const int lane = tid & 31;
    const int warp = tid >> 5;
    const int warp_m = warp >> 2;
    const int warp_n = warp & 3;
    const int m0 = blockIdx.x * 128;
    const int n0 = blockIdx.y * NT;

    {
        float* wa_s = (float*)(smem + OFF_WA);
        float* hp_s = (float*)(smem + OFF_HP);
        for (int i = tid; i < NT; i += 512) wa_s[i] = wa[n0 + i];
        int nb = 128 / rpb; if (nb < 1) nb = 1;
        int b0 = m0 / rpb;
        for (int i = tid; i < nb * NT; i += 512)
            hp_s[i] = hproj[(size_t)(b0 + i / NT) * 1024 + n0 + (i % NT)];
    }

    const __half* Abase = A + (size_t)m0 * K;
    const __half* Wbase = W + (size_t)n0 * K;

    float acc[2][NI][4];
    #pragma unroll
    for (int i = 0; i < 2; i++)
        #pragma unroll
        for (int j = 0; j < NI; j++)
            #pragma unroll
            for (int q = 0; q < 4; q++) acc[i][j][q] = 0.f;

    const int lrow = lane & 15;
    const int lhi  = lane >> 4;
    uint32_t a_off[2], b_off[NI / 2];
    #pragma unroll
    for (int mi = 0; mi < 2; mi++)
        a_off[mi] = tile_off(warp_m * 32 + mi * 16 + lrow, lhi);
    #pragma unroll
    for (int p = 0; p < NI / 2; p++)
        b_off[p] = 16384u + tile_off(warp_n * WN + p * 16 + lrow, lhi);

    GEMM_MAINLOOP(NT, NI, Abase, Wbase, K)

    // ---- epilogue: tanh + weighted column reduction ----
    const float* wa_s = (const float*)(smem + OFF_WA);
    const float* hp_s = (const float*)(smem + OFF_HP);
    const int g = lane >> 2, tig = lane & 3;

    #pragma unroll
    for (int mi = 0; mi < 2; mi++) {
        int r0 = warp_m * 32 + mi * 16 + g;
        int r1 = r0 + 8;
        int bl0 = r0 / rpb, bl1 = r1 / rpb;
        const float* hp0 = hp_s + bl0 * NT;
        const float* hp1 = hp_s + bl1 * NT;
        float s0 = 0.f, s1 = 0.f;
        #pragma unroll
        for (int ni = 0; ni < NI; ni++) {
            int cl = warp_n * WN + ni * 8 + 2 * tig;
            float w0 = wa_s[cl], w1 = wa_s[cl + 1];
            float t;
            asm("tanh.approx.f32 %0, %1;" : "=f"(t) : "f"(acc[mi][ni][0] + hp0[cl]));     s0 += t * w0;
            asm("tanh.approx.f32 %0, %1;" : "=f"(t) : "f"(acc[mi][ni][1] + hp0[cl + 1])); s0 += t * w1;
            asm("tanh.approx.f32 %0, %1;" : "=f"(t) : "f"(acc[mi][ni][2] + hp1[cl]));     s1 += t * w0;
            asm("tanh.approx.f32 %0, %1;" : "=f"(t) : "f"(acc[mi][ni][3] + hp1[cl + 1])); s1 += t * w1;
        }
        s0 += __shfl_xor_sync(0xffffffffu, s0, 1);
        s0 += __shfl_xor_sync(0xffffffffu, s0, 2);
        s1 += __shfl_xor_sync(0xffffffffu, s1, 1);
        s1 += __shfl_xor_sync(0xffffffffu, s1, 2);
        if (tig == 0) {
            atomicAdd(&score[m0 + r0], s0);
            atomicAdd(&score[m0 + r1], s1);
        }
    }
}

// ================= GEMM + bias store (hproj) =================
// out[m, n0+cl] = acc + bh[cl] + bv[cl], rows m < 64 only. blockIdx.y: [0,4) -> s, [4,8) -> t.
__global__ __launch_bounds__(512, 1) void gemm_bias_mma(
    const __half* __restrict__ A,
    const __half* __restrict__ Ws, const float* __restrict__ bh_s,
    const float* __restrict__ bv_s, float* __restrict__ out_s,
    const __half* __restrict__ Wt, const float* __restrict__ bh_t,
    const float* __restrict__ bv_t, float* __restrict__ out_t)
{
    constexpr int NT = 256, WN = 64, NI = 8, K = HIDDEN;
    constexpr int OFF_B = 4 * (16384 + NT * 128);

    extern __shared__ char smem[];
    const uint32_t sb = smem_u32(smem);
    const int tid = threadIdx.x;
    const int lane = tid & 31;
    const int warp = tid >> 5;
    const int warp_m = warp >> 2;
    const int warp_n = warp & 3;
    const int mat = blockIdx.y >> 2;
    const int n0 = (blockIdx.y & 3) * NT;
    const __half* W = mat ? Wt : Ws;
    const float* bh = mat ? bh_t : bh_s;
    const float* bv = mat ? bv_t : bv_s;
    float* out = mat ? out_t : out_s;

    {
        float* b_s = (float*)(smem + OFF_B);
        for (int i = tid; i < NT; i += 512) b_s[i] = bh[n0 + i] + bv[n0 + i];
    }

    const __half* Abase = A;
    const __half* Wbase = W + (size_t)n0 * K;

    float acc[2][NI][4];
    #pragma unroll
    for (int i = 0; i < 2; i++)
        #pragma unroll
        for (int j = 0; j < NI; j++)
            #pragma unroll
            for (int q = 0; q < 4; q++) acc[i][j][q] = 0.f;

    const int lrow = lane & 15;
    const int lhi  = lane >> 4;
    uint32_t a_off[2], b_off[NI / 2];
    #pragma unroll
    for (int mi = 0; mi < 2; mi++)
        a_off[mi] = tile_off(warp_m * 32 + mi * 16 + lrow, lhi);
    #pragma unroll
    for (int p = 0; p < NI / 2; p++)
        b_off[p] = 16384u + tile_off(warp_n * WN + p * 16 + lrow, lhi);

    GEMM_MAINLOOP(NT, NI, Abase, Wbase, K)

    const float* b_s = (const float*)(smem + OFF_B);
    const int g = lane >> 2, tig = lane & 3;
    #pragma unroll
    for (int mi = 0; mi < 2; mi++) {
        int r0 = warp_m * 32 + mi * 16 + g;
        int r1 = r0 + 8;
        #pragma unroll
        for (int ni = 0; ni < NI; ni++) {
            int cl = warp_n * WN + ni * 8 + 2 * tig;
            if (r0 < 64) {
                out[r0 * 1024 + n0 + cl]     = acc[mi][ni][0] + b_s[cl];
                out[r0 * 1024 + n0 + cl + 1] = acc[mi][ni][1] + b_s[cl + 1];
            }
            if (r1 < 64) {
                out[r1 * 1024 + n0 + cl]     = acc[mi][ni][2] + b_s[cl];
                out[r1 * 1024 + n0 + cl + 1] = acc[mi][ni][3] + b_s[cl + 1];
            }
        }
    }
}

// ================= small kernels =================
__global__ void zero_kernel(float* __restrict__ p, int n) {
    int i = blockIdx.x * blockDim.x + threadIdx.x;
    if (i < n) p[i] = 0.0f;
}

__global__ __launch_bounds__(256) void cvt_f2h(const float* __restrict__ in,
                                               __half* __restrict__ out, int n) {
    int i = (blockIdx.x * blockDim.x + threadIdx.x) * 4;
    if (i < n) {
        float4 v = *(const float4*)(in + i);
        __half2* o = (__half2*)(out + i);
        o[0] = __floats2half2_rn(v.x, v.y);
        o[1] = __floats2half2_rn(v.z, v.w);
    }
}

// hidden [64,1024] f32 -> [128,1024] f16 (rows 64..127 zero)
__global__ __launch_bounds__(256) void cvt_hid_pad(const float* __restrict__ in,
                                                   __half* __restrict__ out) {
    int i = (blockIdx.x * blockDim.x + threadIdx.x) * 4;   // over 128*1024
    if (i < 128 * HIDDEN) {
        __half2* o = (__half2*)(out + i);
        if (i < 64 * HIDDEN) {
            float4 v = *(const float4*)(in + i);
            o[0] = __floats2half2_rn(v.x, v.y);
            o[1] = __floats2half2_rn(v.z, v.w);
        } else {
            o[0] = __floats2half2_rn(0.f, 0.f);
            o[1] = __floats2half2_rn(0.f, 0.f);
        }
    }
}

// spatial softmax + weighted object sum (fp16 obj read) + concat
__global__ __launch_bounds__(256) void spatial_kernel(
    const __half* __restrict__ obj_h, const float* __restrict__ frame,
    const float* __restrict__ score, float* __restrict__ feat,
    __half* __restrict__ feat_h)
{
    int bf = blockIdx.x;
    __shared__ float alpha[NN];
    if (threadIdx.x == 0) {
        float s[NN];
        float mx = -1e30f;
        #pragma unroll
        for (int n = 0; n < NN; n++) { s[n] = score[bf * NN + n]; mx = fmaxf(mx, s[n]); }
        float sum = 0.f;
        #pragma unroll
        for (int n = 0; n < NN; n++) { float e = expf(s[n] - mx); alpha[n] = e; sum += e; }
        float inv = 1.f / sum;
        #pragma unroll
        for (int n = 0; n < NN; n++) alpha[n] *= inv;
    }
    __syncthreads();

    const __half2* base = (const __half2*)(obj_h + (size_t)bf * NN * REGION);
    float* frow = feat + (size_t)bf * FEAT2;
    __half2* hrow2 = (__half2*)(feat_h + (size_t)bf * FEAT2);
    for (int d2 = threadIdx.x; d2 < REGION / 2; d2 += 256) {
        float ax = 0.f, ay = 0.f;
        #pragma unroll 6
        for (int n = 0; n < NN; n++) {
            float2 v = __half22float2(base[n * (REGION / 2) + d2]);
            ax += alpha[n] * v.x;
            ay += alpha[n] * v.y;
        }
        frow[2 * d2] = ax;
        frow[2 * d2 + 1] = ay;
        hrow2[d2] = __floats2half2_rn(ax, ay);
    }
    const float* frm = frame + (size_t)bf * (2 * HIDDEN);
    for (int d = threadIdx.x; d < 2 * HIDDEN; d += 256) {
        float v = frm[d];
        frow[REGION + d] = v;
        feat_h[(size_t)bf * FEAT2 + REGION + d] = __float2half_rn(v);
    }
}

__global__ __launch_bounds__(256) void temporal_kernel(
    const float* __restrict__ feat, const float* __restrict__ score2,
    float* __restrict__ out)
{
    int b = blockIdx.x;
    __shared__ float beta[FF];
    if (threadIdx.x == 0) {
        float s[FF];
        float mx = -1e30f;
        #pragma unroll
        for (int f = 0; f < FF; f++) { s[f] = score2[b * FF + f]; mx = fmaxf(mx, s[f]); }
        float sum = 0.f;
        #pragma unroll
        for (int f = 0; f < FF; f++) { float e = expf(s[f] - mx); beta[f] = e; sum += e; }
        float inv = 1.f / sum;
        #pragma unroll
        for (int f = 0; f < FF; f++) beta[f] *= inv;
    }
    __syncthreads();

    int d0 = blockIdx.y * (FEAT2 / 4);
    for (int d = d0 + threadIdx.x; d < d0 + FEAT2 / 4; d += 256) {
        float acc = 0.f;
        #pragma unroll 8
        for (int f = 0; f < FF; f++)
            acc += beta[f] * feat[((size_t)b * FF + f) * FEAT2 + d];
        out[(size_t)b * FEAT2 + d] = acc;
    }
}

// ================= launch =================
extern "C" void kernel_launch(void* const* d_in, const int* in_sizes, int n_in,
                              void* d_out, int out_size)
{
    const float* frame  = (const float*)d_in[0];
    const float* obj    = (const float*)d_in[1];
    const float* hidden = (const float*)d_in[2];
    const float* s_wh_w = (const float*)d_in[3];
    const float* s_wh_b = (const float*)d_in[4];
    const float* s_wv_w = (const float*)d_in[5];
    const float* s_wv_b = (const float*)d_in[6];
    const float* s_wa_w = (const float*)d_in[7];
    const float* t_wh_w = (const float*)d_in[8];
    const float* t_wh_b = (const float*)d_in[9];
    const float* t_wv_w = (const float*)d_in[10];
    const float* t_wv_b = (const float*)d_in[11];
    const float* t_wa_w = (const float*)d_in[12];
    float* out = (float*)d_out;

    float *p_hs, *p_ht, *p_s1, *p_feat, *p_s2;
    __half *p_obj_h, *p_feat_h, *p_swv_h, *p_twv_h, *p_swh_h, *p_twh_h, *p_hid_h;
    cudaGetSymbolAddress((void**)&p_hs, g_hproj_s);
    cudaGetSymbolAddress((void**)&p_ht, g_hproj_t);
    cudaGetSymbolAddress((void**)&p_s1, g_score1);
    cudaGetSymbolAddress((void**)&p_feat, g_feat);
    cudaGetSymbolAddress((void**)&p_s2, g_score2);
    cudaGetSymbolAddress((void**)&p_obj_h, g_obj_h);
    cudaGetSymbolAddress((void**)&p_feat_h, g_feat_h);
    cudaGetSymbolAddress((void**)&p_swv_h, g_swv_h);
    cudaGetSymbolAddress((void**)&p_twv_h, g_twv_h);
    cudaGetSymbolAddress((void**)&p_swh_h, g_swh_h);
    cudaGetSymbolAddress((void**)&p_twh_h, g_twh_h);
    cudaGetSymbolAddress((void**)&p_hid_h, g_hid_h);

    // smem: 4*(16384 + NT*128) + NT*4 + 4*NT*4
    const int SMEM_256 = 4 * (16384 + 256 * 128) + 256 * 4 + 4 * 256 * 4;   // 201728
    const int SMEM_128 = 4 * (16384 + 128 * 128) + 128 * 4 + 4 * 128 * 4;   // 133632
    const int SMEM_B   = 4 * (16384 + 256 * 128) + 256 * 4;                 // 197632
    cudaFuncSetAttribute(gemm_score_mma<256>, cudaFuncAttributeMaxDynamicSharedMemorySize, SMEM_256);
    cudaFuncSetAttribute(gemm_score_mma<128>, cudaFuncAttributeMaxDynamicSharedMemorySize, SMEM_128);
    cudaFuncSetAttribute(gemm_bias_mma, cudaFuncAttributeMaxDynamicSharedMemorySize, SMEM_B);

    // fp16 conversions
    {
        int n_swh = 1024 * HIDDEN;
        cvt_f2h<<<(n_swh / 4 + 255) / 256, 256>>>(s_wh_w, p_swh_h, n_swh);
        cvt_f2h<<<(n_swh / 4 + 255) / 256, 256>>>(t_wh_w, p_twh_h, n_swh);
        cvt_hid_pad<<<(128 * HIDDEN / 4 + 255) / 256, 256>>>(hidden, p_hid_h);
        int n_swv = 1024 * REGION;
        cvt_f2h<<<(n_swv / 4 + 255) / 256, 256>>>(s_wv_w, p_swv_h, n_swv);
        int n_twv = 1024 * FEAT2;
        cvt_f2h<<<(n_twv / 4 + 255) / 256, 256>>>(t_wv_w, p_twv_h, n_twv);
        int n_obj = M1 * REGION;
        cvt_f2h<<<(n_obj / 4 + 255) / 256, 256>>>(obj, p_obj_h, n_obj);
    }

    // hidden-state projections as one mma GEMM launch (both matrices)
    gemm_bias_mma<<<dim3(1, 8), 512, SMEM_B>>>(p_hid_h,
                                               p_swh_h, s_wh_b, s_wv_b, p_hs,
                                               p_twh_h, t_wh_b, t_wv_b, p_ht);

    // spatial attention scores: 155 GFLOP fp16 mma GEMM, fused tanh-dot epilogue
    zero_kernel<<<(M1 + 255) / 256, 256>>>(p_s1, M1);
    gemm_score_mma<256><<<dim3(M1 / 128, 4), 512, SMEM_256>>>(
        p_obj_h, p_swv_h, p_hs, s_wa_w, p_s1, REGION, FF * NN);

    // softmax over boxes + weighted object sum (fp16 obj) + concat frame feats
    spatial_kernel<<<M2, 256>>>(p_obj_h, frame, p_s1, p_feat, p_feat_h);

    // temporal attention scores
    zero_kernel<<<(M2 + 255) / 256, 256>>>(p_s2, M2);
    gemm_score_mma<128><<<dim3(M2 / 128, 8), 512, SMEM_128>>>(
        p_feat_h, p_twv_h, p_ht, t_wa_w, p_s2, FEAT2, FF);

    // softmax over frames + weighted feat sum -> [64, 3072]
    temporal_kernel<<<dim3(BB, 4), 256>>>(p_feat, p_s2, out);
}

// round 11
// speedup vs baseline: 4.1816x; 1.0180x over previous
#include <cuda_runtime.h>
#include <cuda_fp16.h>
#include <math.h>
#include <stdint.h>

// Problem constants
#define BB   64
#define FF   32
#define NN   36
#define REGION 1024
#define HIDDEN 1024
#define FEAT2  3072
#define M1   (BB*FF*NN)       // 73728 rows of spatial GEMM
#define M2   (BB*FF)          // 2048 rows of temporal GEMM

// ---------------- scratch (device globals; no allocation allowed) ----------------
__device__ float  g_hproj_s[BB * 1024];
__device__ float  g_hproj_t[BB * 1024];
__device__ float  g_score1[M1];
__device__ float  g_feat[M2 * FEAT2];
__device__ float  g_score2[M2];
__device__ __half g_obj_h[(size_t)M1 * REGION];     // fp16 object_feats
__device__ __half g_feat_h[(size_t)M2 * FEAT2];     // fp16 feat
__device__ __half g_swv_h[1024 * REGION];           // fp16 s_wv_w
__device__ __half g_twv_h[1024 * FEAT2];            // fp16 t_wv_w
__device__ __half g_swh_h[1024 * HIDDEN];           // fp16 s_wh_w
__device__ __half g_twh_h[1024 * HIDDEN];           // fp16 t_wh_w
__device__ __half g_hid_h[128 * HIDDEN];            // fp16 hidden, padded to 128 rows

// ================= PTX helpers =================
__device__ __forceinline__ uint32_t smem_u32(const void* p) {
    uint32_t a;
    asm("{ .reg .u64 t; cvta.to.shared.u64 t, %1; cvt.u32.u64 %0, t; }" : "=r"(a) : "l"(p));
    return a;
}

__device__ __forceinline__ void cp_async16(uint32_t dst, const void* src) {
    asm volatile("cp.async.cg.shared.global [%0], [%1], 16;" :: "r"(dst), "l"(src));
}
#define CP_COMMIT() asm volatile("cp.async.commit_group;" ::: "memory")

__device__ __forceinline__ void ldsm_x4(uint32_t r[4], uint32_t addr) {
    asm volatile("ldmatrix.sync.aligned.m8n8.x4.shared.b16 {%0,%1,%2,%3}, [%4];"
                 : "=r"(r[0]), "=r"(r[1]), "=r"(r[2]), "=r"(r[3]) : "r"(addr));
}

__device__ __forceinline__ void mma_f16(float c[4], const uint32_t a[4], uint32_t b0, uint32_t b1) {
    asm volatile(
        "mma.sync.aligned.m16n8k16.row.col.f32.f16.f16.f32 "
        "{%0,%1,%2,%3}, {%4,%5,%6,%7}, {%8,%9}, {%0,%1,%2,%3};"
        : "+f"(c[0]), "+f"(c[1]), "+f"(c[2]), "+f"(c[3])
        : "r"(a[0]), "r"(a[1]), "r"(a[2]), "r"(a[3]), "r"(b0), "r"(b1));
}

__device__ __forceinline__ uint32_t h2_bits(__half2 h) {
    uint32_t u;
    memcpy(&u, &h, 4);
    return u;
}

// swizzled offset within a [rows x 64 half] tile (128B rows, SW128 pattern)
__device__ __forceinline__ uint32_t tile_off(int row, int chunk16) {
    return (uint32_t)(row * 128 + ((chunk16 ^ (row & 7)) << 4));
}

// per-stage tile loader: A 128 rows x 64 halves + B NT rows x 64 halves
template <int NT>
__device__ __forceinline__ void load_stage(uint32_t base, const __half* Ag, const __half* Wg,
                                           int K, int tid) {
    #pragma unroll
    for (int it = 0; it < (1024 + NT * 8) / 512; it++) {
        int id = tid + it * 512;
        uint32_t dst; const __half* src;
        if (id < 1024) {
            int r = id >> 3, c = id & 7;
            dst = base + tile_off(r, c);
            src = Ag + (size_t)r * K + c * 8;
        } else {
            int j = id - 1024;
            int r = j >> 3, c = j & 7;
            dst = base + 16384 + tile_off(r, c);
            src = Wg + (size_t)r * K + c * 8;
        }
        cp_async16(dst, src);
    }
}

// ======== fp16 mma GEMM mainloop (4-stage, single sync per K-chunk) ========
#define GEMM_MAINLOOP(NT, NI, Abase, Wbase, K)                                        \
    const int S = (K) >> 6;                                                            \
    constexpr int STAGE = 16384 + (NT) * 128;                                          \
    load_stage<NT>(sb + 0 * STAGE, (Abase) +   0, (Wbase) +   0, (K), tid); CP_COMMIT();\
    load_stage<NT>(sb + 1 * STAGE, (Abase) +  64, (Wbase) +  64, (K), tid); CP_COMMIT();\
    load_stage<NT>(sb + 2 * STAGE, (Abase) + 128, (Wbase) + 128, (K), tid); CP_COMMIT();\
    for (int kc = 0; kc < S; kc++) {                                                   \
        if (kc + 3 < S)                                                                \
            load_stage<NT>(sb + ((kc + 3) & 3) * STAGE,                                \
                           (Abase) + (kc + 3) * 64, (Wbase) + (kc + 3) * 64, (K), tid);\
        CP_COMMIT();                                                                   \
        asm volatile("cp.async.wait_group 3;" ::: "memory");                           \
        __syncthreads();                                                               \
        const uint32_t stage_base = sb + (kc & 3) * STAGE;                             \
        _Pragma("unroll")                                                              \
        for (int s = 0; s < 4; s++) {                                                  \
            const uint32_t x = (uint32_t)s << 5;                                       \
            uint32_t af[2][4];                                                         \
            _Pragma("unroll")                                                          \
            for (int mi = 0; mi < 2; mi++)                                             \
                ldsm_x4(af[mi], stage_base + (a_off[mi] ^ x));                         \
            uint32_t bf[NI][2];                                                        \
            _Pragma("unroll")                                                          \
            for (int p = 0; p < (NI) / 2; p++) {                                       \
                uint32_t r[4];                                                         \
                ldsm_x4(r, stage_base + (b_off[p] ^ x));                               \
                bf[2*p][0] = r[0]; bf[2*p][1] = r[2];                                  \
                bf[2*p+1][0] = r[1]; bf[2*p+1][1] = r[3];                              \
            }                                                                          \
            _Pragma("unroll")                                                          \
            for (int mi = 0; mi < 2; mi++)                                             \
                _Pragma("unroll")                                                      \
                for (int ni = 0; ni < (NI); ni++)                                      \
                    mma_f16(acc[mi][ni], af[mi], bf[ni][0], bf[ni][1]);                \
        }                                                                              \
    }

// ================= GEMM + tanh-dot epilogue =================
// grid: x = n-block (fast; consecutive CTAs share one A tile -> L2 reuse),
//       y = m-block.
template <int NT>
__global__ __launch_bounds__(512, 1) void gemm_score_mma(
    const __half* __restrict__ A, const __half* __restrict__ W,
    const float* __restrict__ hproj, const float* __restrict__ wa,
    float* __restrict__ score, int K, int rpb)
{
    constexpr int WN = NT / 4;
    constexpr int NI = WN / 8;
    constexpr int OFF_WA = 4 * (16384 + NT * 128);
    constexpr int OFF_HP = OFF_WA + NT * 4;

    extern __shared__ char smem[];
    const uint32_t sb = smem_u32(smem);
    const int tid = threadIdx.x;
    const int lane = tid & 31;
    const int warp = tid >> 5;
    const int warp_m = warp >> 2;
    const int warp_n = warp & 3;
    const int m0 = blockIdx.y * 128;
    const int n0 = blockIdx.x * NT;

    {
        float* wa_s = (float*)(smem + OFF_WA);
        float* hp_s = (float*)(smem + OFF_HP);
        for (int i = tid; i < NT; i += 512) wa_s[i] = wa[n0 + i];
        int nb = 128 / rpb; if (nb < 1) nb = 1;
        int b0 = m0 / rpb;
        for (int i = tid; i < nb * NT; i += 512)
            hp_s[i] = hproj[(size_t)(b0 + i / NT) * 1024 + n0 + (i % NT)];
    }

    const __half* Abase = A + (size_t)m0 * K;
    const __half* Wbase = W + (size_t)n0 * K;

    float acc[2][NI][4];
    #pragma unroll
    for (int i = 0; i < 2; i++)
        #pragma unroll
        for (int j = 0; j < NI; j++)
            #pragma unroll
            for (int q = 0; q < 4; q++) acc[i][j][q] = 0.f;

    const int lrow = lane & 15;
    const int lhi  = lane >> 4;
    uint32_t a_off[2], b_off[NI / 2];
    #pragma unroll
    for (int mi = 0; mi < 2; mi++)
        a_off[mi] = tile_off(warp_m * 32 + mi * 16 + lrow, lhi);
    #pragma unroll
    for (int p = 0; p < NI / 2; p++)
        b_off[p] = 16384u + tile_off(warp_n * WN + p * 16 + lrow, lhi);

    GEMM_MAINLOOP(NT, NI, Abase, Wbase, K)

    // ---- epilogue: tanh + weighted column reduction ----
    const float* wa_s = (const float*)(smem + OFF_WA);
    const float* hp_s = (const float*)(smem + OFF_HP);
    const int g = lane >> 2, tig = lane & 3;

    #pragma unroll
    for (int mi = 0; mi < 2; mi++) {
        int r0 = warp_m * 32 + mi * 16 + g;
        int r1 = r0 + 8;
        int bl0 = r0 / rpb, bl1 = r1 / rpb;
        const float* hp0 = hp_s + bl0 * NT;
        const float* hp1 = hp_s + bl1 * NT;
        float s0 = 0.f, s1 = 0.f;
        #pragma unroll
        for (int ni = 0; ni < NI; ni++) {
            int cl = warp_n * WN + ni * 8 + 2 * tig;
            float w0 = wa_s[cl], w1 = wa_s[cl + 1];
            float t;
            asm("tanh.approx.f32 %0, %1;" : "=f"(t) : "f"(acc[mi][ni][0] + hp0[cl]));     s0 += t * w0;
            asm("tanh.approx.f32 %0, %1;" : "=f"(t) : "f"(acc[mi][ni][1] + hp0[cl + 1])); s0 += t * w1;
            asm("tanh.approx.f32 %0, %1;" : "=f"(t) : "f"(acc[mi][ni][2] + hp1[cl]));     s1 += t * w0;
            asm("tanh.approx.f32 %0, %1;" : "=f"(t) : "f"(acc[mi][ni][3] + hp1[cl + 1])); s1 += t * w1;
        }
        s0 += __shfl_xor_sync(0xffffffffu, s0, 1);
        s0 += __shfl_xor_sync(0xffffffffu, s0, 2);
        s1 += __shfl_xor_sync(0xffffffffu, s1, 1);
        s1 += __shfl_xor_sync(0xffffffffu, s1, 2);
        if (tig == 0) {
            atomicAdd(&score[m0 + r0], s0);
            atomicAdd(&score[m0 + r1], s1);
        }
    }
}

// ================= GEMM + bias store (hproj) =================
__global__ __launch_bounds__(512, 1) void gemm_bias_mma(
    const __half* __restrict__ A,
    const __half* __restrict__ Ws, const float* __restrict__ bh_s,
    const float* __restrict__ bv_s, float* __restrict__ out_s,
    const __half* __restrict__ Wt, const float* __restrict__ bh_t,
    const float* __restrict__ bv_t, float* __restrict__ out_t)
{
    constexpr int NT = 256, WN = 64, NI = 8, K = HIDDEN;
    constexpr int OFF_B = 4 * (16384 + NT * 128);

    extern __shared__ char smem[];
    const uint32_t sb = smem_u32(smem);
    const int tid = threadIdx.x;
    const int lane = tid & 31;
    const int warp = tid >> 5;
    const int warp_m = warp >> 2;
    const int warp_n = warp & 3;
    const int mat = blockIdx.y >> 2;
    const int n0 = (blockIdx.y & 3) * NT;
    const __half* W = mat ? Wt : Ws;
    const float* bh = mat ? bh_t : bh_s;
    const float* bv = mat ? bv_t : bv_s;
    float* out = mat ? out_t : out_s;

    {
        float* b_s = (float*)(smem + OFF_B);
        for (int i = tid; i < NT; i += 512) b_s[i] = bh[n0 + i] + bv[n0 + i];
    }

    const __half* Abase = A;
    const __half* Wbase = W + (size_t)n0 * K;

    float acc[2][NI][4];
    #pragma unroll
    for (int i = 0; i < 2; i++)
        #pragma unroll
        for (int j = 0; j < NI; j++)
            #pragma unroll
            for (int q = 0; q < 4; q++) acc[i][j][q] = 0.f;

    const int lrow = lane & 15;
    const int lhi  = lane >> 4;
    uint32_t a_off[2], b_off[NI / 2];
    #pragma unroll
    for (int mi = 0; mi < 2; mi++)
        a_off[mi] = tile_off(warp_m * 32 + mi * 16 + lrow, lhi);
    #pragma unroll
    for (int p = 0; p < NI / 2; p++)
        b_off[p] = 16384u + tile_off(warp_n * WN + p * 16 + lrow, lhi);

    GEMM_MAINLOOP(NT, NI, Abase, Wbase, K)

    const float* b_s = (const float*)(smem + OFF_B);
    const int g = lane >> 2, tig = lane & 3;
    #pragma unroll
    for (int mi = 0; mi < 2; mi++) {
        int r0 = warp_m * 32 + mi * 16 + g;
        int r1 = r0 + 8;
        #pragma unroll
        for (int ni = 0; ni < NI; ni++) {
            int cl = warp_n * WN + ni * 8 + 2 * tig;
            if (r0 < 64) {
                out[r0 * 1024 + n0 + cl]     = acc[mi][ni][0] + b_s[cl];
                out[r0 * 1024 + n0 + cl + 1] = acc[mi][ni][1] + b_s[cl + 1];
            }
            if (r1 < 64) {
                out[r1 * 1024 + n0 + cl]     = acc[mi][ni][2] + b_s[cl];
                out[r1 * 1024 + n0 + cl + 1] = acc[mi][ni][3] + b_s[cl + 1];
            }
        }
    }
}

// ================= small kernels =================
__global__ void zero_kernel(float* __restrict__ p, int n) {
    int i = blockIdx.x * blockDim.x + threadIdx.x;
    if (i < n) p[i] = 0.0f;
}

// f32 -> f16, 8 elements per thread (2x LDG.128 + 1x STG.128), n % 8 == 0
__global__ __launch_bounds__(256) void cvt_f2h8(const float* __restrict__ in,
                                                __half* __restrict__ out, int n) {
    int i = (blockIdx.x * blockDim.x + threadIdx.x) * 8;
    if (i < n) {
        float4 v0 = *(const float4*)(in + i);
        float4 v1 = *(const float4*)(in + i + 4);
        uint4 o;
        o.x = h2_bits(__floats2half2_rn(v0.x, v0.y));
        o.y = h2_bits(__floats2half2_rn(v0.z, v0.w));
        o.z = h2_bits(__floats2half2_rn(v1.x, v1.y));
        o.w = h2_bits(__floats2half2_rn(v1.z, v1.w));
        *(uint4*)(out + i) = o;
    }
}

// hidden [64,1024] f32 -> [128,1024] f16 (rows 64..127 zero)
__global__ __launch_bounds__(256) void cvt_hid_pad(const float* __restrict__ in,
                                                   __half* __restrict__ out) {
    int i = (blockIdx.x * blockDim.x + threadIdx.x) * 4;
    if (i < 128 * HIDDEN) {
        __half2* o = (__half2*)(out + i);
        if (i < 64 * HIDDEN) {
            float4 v = *(const float4*)(in + i);
            o[0] = __floats2half2_rn(v.x, v.y);
            o[1] = __floats2half2_rn(v.z, v.w);
        } else {
            o[0] = __floats2half2_rn(0.f, 0.f);
            o[1] = __floats2half2_rn(0.f, 0.f);
        }
    }
}

// spatial softmax + weighted object sum (fp16 obj read) + concat
__global__ __launch_bounds__(256) void spatial_kernel(
    const __half* __restrict__ obj_h, const float* __restrict__ frame,
    const float* __restrict__ score, float* __restrict__ feat,
    __half* __restrict__ feat_h)
{
    int bf = blockIdx.x;
    __shared__ float alpha[NN];
    if (threadIdx.x == 0) {
        float s[NN];
        float mx = -1e30f;
        #pragma unroll
        for (int n = 0; n < NN; n++) { s[n] = score[bf * NN + n]; mx = fmaxf(mx, s[n]); }
        float sum = 0.f;
        #pragma unroll
        for (int n = 0; n < NN; n++) { float e = expf(s[n] - mx); alpha[n] = e; sum += e; }
        float inv = 1.f / sum;
        #pragma unroll
        for (int n = 0; n < NN; n++) alpha[n] *= inv;
    }
    __syncthreads();

    const __half2* base = (const __half2*)(obj_h + (size_t)bf * NN * REGION);
    float* frow = feat + (size_t)bf * FEAT2;
    __half2* hrow2 = (__half2*)(feat_h + (size_t)bf * FEAT2);
    for (int d2 = threadIdx.x; d2 < REGION / 2; d2 += 256) {
        float ax = 0.f, ay = 0.f;
        #pragma unroll 6
        for (int n = 0; n < NN; n++) {
            float2 v = __half22float2(base[n * (REGION / 2) + d2]);
            ax += alpha[n] * v.x;
            ay += alpha[n] * v.y;
        }
        frow[2 * d2] = ax;
        frow[2 * d2 + 1] = ay;
        hrow2[d2] = __floats2half2_rn(ax, ay);
    }
    const float* frm = frame + (size_t)bf * (2 * HIDDEN);
    for (int d = threadIdx.x; d < 2 * HIDDEN; d += 256) {
        float v = frm[d];
        frow[REGION + d] = v;
        feat_h[(size_t)bf * FEAT2 + REGION + d] = __float2half_rn(v);
    }
}

__global__ __launch_bounds__(256) void temporal_kernel(
    const float* __restrict__ feat, const float* __restrict__ score2,
    float* __restrict__ out)
{
    int b = blockIdx.x;
    __shared__ float beta[FF];
    if (threadIdx.x == 0) {
        float s[FF];
        float mx = -1e30f;
        #pragma unroll
        for (int f = 0; f < FF; f++) { s[f] = score2[b * FF + f]; mx = fmaxf(mx, s[f]); }
        float sum = 0.f;
        #pragma unroll
        for (int f = 0; f < FF; f++) { float e = expf(s[f] - mx); beta[f] = e; sum += e; }
        float inv = 1.f / sum;
        #pragma unroll
        for (int f = 0; f < FF; f++) beta[f] *= inv;
    }
    __syncthreads();

    int d0 = blockIdx.y * (FEAT2 / 4);
    for (int d = d0 + threadIdx.x; d < d0 + FEAT2 / 4; d += 256) {
        float acc = 0.f;
        #pragma unroll 8
        for (int f = 0; f < FF; f++)
            acc += beta[f] * feat[((size_t)b * FF + f) * FEAT2 + d];
        out[(size_t)b * FEAT2 + d] = acc;
    }
}

// ================= launch =================
extern "C" void kernel_launch(void* const* d_in, const int* in_sizes, int n_in,
                              void* d_out, int out_size)
{
    const float* frame  = (const float*)d_in[0];
    const float* obj    = (const float*)d_in[1];
    const float* hidden = (const float*)d_in[2];
    const float* s_wh_w = (const float*)d_in[3];
    const float* s_wh_b = (const float*)d_in[4];
    const float* s_wv_w = (const float*)d_in[5];
    const float* s_wv_b = (const float*)d_in[6];
    const float* s_wa_w = (const float*)d_in[7];
    const float* t_wh_w = (const float*)d_in[8];
    const float* t_wh_b = (const float*)d_in[9];
    const float* t_wv_w = (const float*)d_in[10];
    const float* t_wv_b = (const float*)d_in[11];
    const float* t_wa_w = (const float*)d_in[12];
    float* out = (float*)d_out;

    float *p_hs, *p_ht, *p_s1, *p_feat, *p_s2;
    __half *p_obj_h, *p_feat_h, *p_swv_h, *p_twv_h, *p_swh_h, *p_twh_h, *p_hid_h;
    cudaGetSymbolAddress((void**)&p_hs, g_hproj_s);
    cudaGetSymbolAddress((void**)&p_ht, g_hproj_t);
    cudaGetSymbolAddress((void**)&p_s1, g_score1);
    cudaGetSymbolAddress((void**)&p_feat, g_feat);
    cudaGetSymbolAddress((void**)&p_s2, g_score2);
    cudaGetSymbolAddress((void**)&p_obj_h, g_obj_h);
    cudaGetSymbolAddress((void**)&p_feat_h, g_feat_h);
    cudaGetSymbolAddress((void**)&p_swv_h, g_swv_h);
    cudaGetSymbolAddress((void**)&p_twv_h, g_twv_h);
    cudaGetSymbolAddress((void**)&p_swh_h, g_swh_h);
    cudaGetSymbolAddress((void**)&p_twh_h, g_twh_h);
    cudaGetSymbolAddress((void**)&p_hid_h, g_hid_h);

    const int SMEM_256 = 4 * (16384 + 256 * 128) + 256 * 4 + 4 * 256 * 4;   // 201728
    const int SMEM_128 = 4 * (16384 + 128 * 128) + 128 * 4 + 4 * 128 * 4;   // 133632
    const int SMEM_B   = 4 * (16384 + 256 * 128) + 256 * 4;                 // 197632
    cudaFuncSetAttribute(gemm_score_mma<256>, cudaFuncAttributeMaxDynamicSharedMemorySize, SMEM_256);
    cudaFuncSetAttribute(gemm_score_mma<128>, cudaFuncAttributeMaxDynamicSharedMemorySize, SMEM_128);
    cudaFuncSetAttribute(gemm_bias_mma, cudaFuncAttributeMaxDynamicSharedMemorySize, SMEM_B);

    // fp16 conversions (8 elems/thread)
    {
        int n_swh = 1024 * HIDDEN;
        cvt_f2h8<<<(n_swh / 8 + 255) / 256, 256>>>(s_wh_w, p_swh_h, n_swh);
        cvt_f2h8<<<(n_swh / 8 + 255) / 256, 256>>>(t_wh_w, p_twh_h, n_swh);
        cvt_hid_pad<<<(128 * HIDDEN / 4 + 255) / 256, 256>>>(hidden, p_hid_h);
        int n_swv = 1024 * REGION;
        cvt_f2h8<<<(n_swv / 8 + 255) / 256, 256>>>(s_wv_w, p_swv_h, n_swv);
        int n_twv = 1024 * FEAT2;
        cvt_f2h8<<<(n_twv / 8 + 255) / 256, 256>>>(t_wv_w, p_twv_h, n_twv);
        int n_obj = M1 * REGION;
        cvt_f2h8<<<(n_obj / 8 + 255) / 256, 256>>>(obj, p_obj_h, n_obj);
    }

    // hidden-state projections as one mma GEMM launch (both matrices)
    gemm_bias_mma<<<dim3(1, 8), 512, SMEM_B>>>(p_hid_h,
                                               p_swh_h, s_wh_b, s_wv_b, p_hs,
                                               p_twh_h, t_wh_b, t_wv_b, p_ht);

    // spatial attention scores: n-blocks fastest for A-tile L2 reuse
    zero_kernel<<<(M1 + 255) / 256, 256>>>(p_s1, M1);
    gemm_score_mma<256><<<dim3(4, M1 / 128), 512, SMEM_256>>>(
        p_obj_h, p_swv_h, p_hs, s_wa_w, p_s1, REGION, FF * NN);

    // softmax over boxes + weighted object sum (fp16 obj) + concat frame feats
    spatial_kernel<<<M2, 256>>>(p_obj_h, frame, p_s1, p_feat, p_feat_h);

    // temporal attention scores (n fastest here too)
    zero_kernel<<<(M2 + 255) / 256, 256>>>(p_s2, M2);
    gemm_score_mma<128><<<dim3(8, M2 / 128), 512, SMEM_128>>>(
        p_feat_h, p_twv_h, p_ht, t_wa_w, p_s2, FEAT2, FF);

    // softmax over frames + weighted feat sum -> [64, 3072]
    temporal_kernel<<<dim3(BB, 4), 256>>>(p_feat, p_s2, out);
}

// round 13
// speedup vs baseline: 4.2567x; 1.0180x over previous
#include <cuda_runtime.h>
#include <cuda_fp16.h>
#include <math.h>
#include <stdint.h>

// Problem constants
#define BB   64
#define FF   32
#define NN   36
#define REGION 1024
#define HIDDEN 1024
#define FEAT2  3072
#define M1   (BB*FF*NN)       // 73728 rows of spatial GEMM
#define M2   (BB*FF)          // 2048 rows of temporal GEMM

// ---------------- scratch (device globals; no allocation allowed) ----------------
__device__ float  g_hproj_s[BB * 1024];
__device__ float  g_hproj_t[BB * 1024];
__device__ float  g_score1[M1];
__device__ float  g_feat[M2 * FEAT2];
__device__ float  g_score2[M2];
__device__ __half g_obj_h[(size_t)M1 * REGION];     // fp16 object_feats
__device__ __half g_feat_h[(size_t)M2 * FEAT2];     // fp16 feat
__device__ __half g_swv_h[1024 * REGION];           // fp16 s_wv_w
__device__ __half g_twv_h[1024 * FEAT2];            // fp16 t_wv_w
__device__ __half g_swh_h[1024 * HIDDEN];           // fp16 s_wh_w
__device__ __half g_twh_h[1024 * HIDDEN];           // fp16 t_wh_w
__device__ __half g_hid_h[128 * HIDDEN];            // fp16 hidden, padded to 128 rows

// ================= PTX helpers =================
__device__ __forceinline__ uint32_t smem_u32(const void* p) {
    uint32_t a;
    asm("{ .reg .u64 t; cvta.to.shared.u64 t, %1; cvt.u32.u64 %0, t; }" : "=r"(a) : "l"(p));
    return a;
}

__device__ __forceinline__ void cp_async16(uint32_t dst, const void* src) {
    asm volatile("cp.async.cg.shared.global [%0], [%1], 16;" :: "r"(dst), "l"(src));
}
#define CP_COMMIT() asm volatile("cp.async.commit_group;" ::: "memory")

__device__ __forceinline__ void ldsm_x4(uint32_t r[4], uint32_t addr) {
    asm volatile("ldmatrix.sync.aligned.m8n8.x4.shared.b16 {%0,%1,%2,%3}, [%4];"
                 : "=r"(r[0]), "=r"(r[1]), "=r"(r[2]), "=r"(r[3]) : "r"(addr));
}

__device__ __forceinline__ void mma_f16(float c[4], const uint32_t a[4], uint32_t b0, uint32_t b1) {
    asm volatile(
        "mma.sync.aligned.m16n8k16.row.col.f32.f16.f16.f32 "
        "{%0,%1,%2,%3}, {%4,%5,%6,%7}, {%8,%9}, {%0,%1,%2,%3};"
        : "+f"(c[0]), "+f"(c[1]), "+f"(c[2]), "+f"(c[3])
        : "r"(a[0]), "r"(a[1]), "r"(a[2]), "r"(a[3]), "r"(b0), "r"(b1));
}

__device__ __forceinline__ uint32_t h2_bits(__half2 h) {
    uint32_t u;
    memcpy(&u, &h, 4);
    return u;
}

// swizzled offset within a [rows x 64 half] tile (128B rows, SW128 pattern)
__device__ __forceinline__ uint32_t tile_off(int row, int chunk16) {
    return (uint32_t)(row * 128 + ((chunk16 ^ (row & 7)) << 4));
}

// per-stage tile loader: A 128 rows x 64 halves + B NT rows x 64 halves
template <int NT>
__device__ __forceinline__ void load_stage(uint32_t base, const __half* Ag, const __half* Wg,
                                           int K, int tid) {
    #pragma unroll
    for (int it = 0; it < (1024 + NT * 8) / 512; it++) {
        int id = tid + it * 512;
        uint32_t dst; const __half* src;
        if (id < 1024) {
            int r = id >> 3, c = id & 7;
            dst = base + tile_off(r, c);
            src = Ag + (size_t)r * K + c * 8;
        } else {
            int j = id - 1024;
            int r = j >> 3, c = j & 7;
            dst = base + 16384 + tile_off(r, c);
            src = Wg + (size_t)r * K + c * 8;
        }
        cp_async16(dst, src);
    }
}

// one K-chunk (4 x k16) of MMAs from a stage buffer
#define GEMM_CHUNK(NI, stage_base)                                                    \
    _Pragma("unroll")                                                                 \
    for (int s = 0; s < 4; s++) {                                                     \
        const uint32_t x = (uint32_t)s << 5;                                          \
        uint32_t af[2][4];                                                            \
        _Pragma("unroll")                                                             \
        for (int mi = 0; mi < 2; mi++)                                                \
            ldsm_x4(af[mi], (stage_base) + (a_off[mi] ^ x));                          \
        uint32_t bf[NI][2];                                                           \
        _Pragma("unroll")                                                             \
        for (int p = 0; p < (NI) / 2; p++) {                                          \
            uint32_t r[4];                                                            \
            ldsm_x4(r, (stage_base) + (b_off[p] ^ x));                                \
            bf[2*p][0] = r[0]; bf[2*p][1] = r[2];                                     \
            bf[2*p+1][0] = r[1]; bf[2*p+1][1] = r[3];                                 \
        }                                                                             \
        _Pragma("unroll")                                                             \
        for (int mi = 0; mi < 2; mi++)                                                \
            _Pragma("unroll")                                                         \
            for (int ni = 0; ni < (NI); ni++)                                         \
                mma_f16(acc[mi][ni], af[mi], bf[ni][0], bf[ni][1]);                   \
    }

// ================= persistent spatial GEMM + tanh-dot epilogue =================
// Each CTA owns mb_per_cta m-blocks; for each it sweeps all NTX n-tiles with a
// never-draining cp.async pipeline, accumulating tanh-dot partials in registers
// across n-tiles; final cross-warp_n reduce through smem -> one plain store/row.
template <int NT, int NTX>
__global__ __launch_bounds__(512, 1) void gemm_score_pers(
    const __half* __restrict__ A, const __half* __restrict__ W,
    const float* __restrict__ hproj, const float* __restrict__ wa,
    float* __restrict__ score, int K, int rpb, int mb_per_cta)
{
    constexpr int WN = NT / 4;
    constexpr int NI = WN / 8;
    constexpr int STAGE = 16384 + NT * 128;
    constexpr int OFF_WA = 4 * STAGE;
    constexpr int OFF_HP = OFF_WA + NT * 4;
    constexpr int OFF_RED = OFF_HP + 4 * NT * 4;

    extern __shared__ char smem[];
    const uint32_t sb = smem_u32(smem);
    const int tid = threadIdx.x;
    const int lane = tid & 31;
    const int warp = tid >> 5;
    const int warp_m = warp >> 2;
    const int warp_n = warp & 3;
    const int G = gridDim.x;
    const int S = K >> 6;

    const int lrow = lane & 15;
    const int lhi  = lane >> 4;
    uint32_t a_off[2], b_off[NI / 2];
    #pragma unroll
    for (int mi = 0; mi < 2; mi++)
        a_off[mi] = tile_off(warp_m * 32 + mi * 16 + lrow, lhi);
    #pragma unroll
    for (int p = 0; p < NI / 2; p++)
        b_off[p] = 16384u + tile_off(warp_n * WN + p * 16 + lrow, lhi);

    // ---- prefetch cursor over the CTA's flat chunk sequence ----
    const int chunks_total = mb_per_cta * NTX * S;
    int pf_kc = 0, pf_nx = 0, pf_mb = blockIdx.x;
    const __half* pfA = A + (size_t)pf_mb * 128 * K;
    const __half* pfW = W;
    int pf_count = 0;

    auto issue_pf = [&](int bufidx) {
        load_stage<NT>(sb + bufidx * STAGE, pfA + pf_kc * 64, pfW + pf_kc * 64, K, tid);
        pf_count++;
        if (++pf_kc == S) {
            pf_kc = 0;
            if (++pf_nx == NTX) {
                pf_nx = 0; pf_mb += G;
                pfA = A + (size_t)pf_mb * 128 * K;
                pfW = W;
            } else {
                pfW += (size_t)NT * K;
            }
        }
    };

    // prologue: fill 3 stages
    #pragma unroll
    for (int q = 0; q < 3; q++) {
        if (pf_count < chunks_total) issue_pf(q);
        CP_COMMIT();
    }

    const int g = lane >> 2, tig = lane & 3;
    int ci = 0;

    for (int mbi = 0; mbi < mb_per_cta; mbi++) {
        const int m0 = (blockIdx.x + mbi * G) * 128;
        float sacc[2][2] = {{0.f, 0.f}, {0.f, 0.f}};

        for (int nx = 0; nx < NTX; nx++) {
            const int n0 = nx * NT;
            // epilogue constants for this tile (ordered vs readers by chunk syncs)
            {
                float* wa_s = (float*)(smem + OFF_WA);
                float* hp_s = (float*)(smem + OFF_HP);
                for (int i = tid; i < NT; i += 512) wa_s[i] = wa[n0 + i];
                int nb = 128 / rpb; if (nb < 1) nb = 1;
                int b0 = m0 / rpb;
                for (int i = tid; i < nb * NT; i += 512)
                    hp_s[i] = hproj[(size_t)(b0 + i / NT) * 1024 + n0 + (i % NT)];
            }

            float acc[2][NI][4];
            #pragma unroll
            for (int i = 0; i < 2; i++)
                #pragma unroll
                for (int j = 0; j < NI; j++)
                    #pragma unroll
                    for (int q = 0; q < 4; q++) acc[i][j][q] = 0.f;

            for (int kc = 0; kc < S; kc++, ci++) {
                if (pf_count < chunks_total) issue_pf((ci + 3) & 3);
                CP_COMMIT();
                asm volatile("cp.async.wait_group 3;" ::: "memory");
                __syncthreads();
                const uint32_t stage_base = sb + (ci & 3) * STAGE;
                GEMM_CHUNK(NI, stage_base)
            }

            // partial epilogue: tanh + weighted col sum, accumulate in regs
            const float* wa_s = (const float*)(smem + OFF_WA);
            const float* hp_s = (const float*)(smem + OFF_HP);
            #pragma unroll
            for (int mi = 0; mi < 2; mi++) {
                int r0 = warp_m * 32 + mi * 16 + g;
                int r1 = r0 + 8;
                int bl0 = r0 / rpb, bl1 = r1 / rpb;
                const float* hp0 = hp_s + bl0 * NT;
                const float* hp1 = hp_s + bl1 * NT;
                float s0 = 0.f, s1 = 0.f;
                #pragma unroll
                for (int ni = 0; ni < NI; ni++) {
                    int cl = warp_n * WN + ni * 8 + 2 * tig;
                    float w0 = wa_s[cl], w1 = wa_s[cl + 1];
                    float t;
                    asm("tanh.approx.f32 %0, %1;" : "=f"(t) : "f"(acc[mi][ni][0] + hp0[cl]));     s0 += t * w0;
                    asm("tanh.approx.f32 %0, %1;" : "=f"(t) : "f"(acc[mi][ni][1] + hp0[cl + 1])); s0 += t * w1;
                    asm("tanh.approx.f32 %0, %1;" : "=f"(t) : "f"(acc[mi][ni][2] + hp1[cl]));     s1 += t * w0;
                    asm("tanh.approx.f32 %0, %1;" : "=f"(t) : "f"(acc[mi][ni][3] + hp1[cl + 1])); s1 += t * w1;
                }
                sacc[mi][0] += s0;
                sacc[mi][1] += s1;
            }
            __syncthreads();   // all readers of wa_s/hp_s done before next tile's load
        }

        // ---- cross-warp_n reduction through smem, then one plain store per row ----
        // Four warps (warp_n=0..3) hold column-slice partials of the SAME 32 rows.
        float* red = (float*)(smem + OFF_RED);
        #pragma unroll
        for (int mi = 0; mi < 2; mi++) {
            float s0 = sacc[mi][0], s1 = sacc[mi][1];
            s0 += __shfl_xor_sync(0xffffffffu, s0, 1);
            s0 += __shfl_xor_sync(0xffffffffu, s0, 2);
            s1 += __shfl_xor_sync(0xffffffffu, s1, 1);
            s1 += __shfl_xor_sync(0xffffffffu, s1, 2);
            if (tig == 0) {
                int r0 = warp_m * 32 + mi * 16 + g;
                red[warp_n * 128 + r0]     = s0;
                red[warp_n * 128 + r0 + 8] = s1;
            }
        }
        __syncthreads();
        for (int r = tid; r < 128; r += 512)
            score[m0 + r] = (red[r] + red[128 + r]) + (red[256 + r] + red[384 + r]);
        __syncthreads();
    }
}

// ================= legacy GEMM + tanh-dot epilogue (temporal; atomics) ==========
template <int NT>
__global__ __launch_bounds__(512, 1) void gemm_score_mma(
    const __half* __restrict__ A, const __half* __restrict__ W,
    const float* __restrict__ hproj, const float* __restrict__ wa,
    float* __restrict__ score, int K, int rpb)
{
    constexpr int WN = NT / 4;
    constexpr int NI = WN / 8;
    constexpr int STAGE = 16384 + NT * 128;
    constexpr int OFF_WA = 4 * STAGE;
    constexpr int OFF_HP = OFF_WA + NT * 4;

    extern __shared__ char smem[];
    const uint32_t sb = smem_u32(smem);
    const int tid = threadIdx.x;
    const int lane = tid & 31;
    const int warp = tid >> 5;
    const int warp_m = warp >> 2;
    const int warp_n = warp & 3;
    const int m0 = blockIdx.y * 128;
    const int n0 = blockIdx.x * NT;
    const int S = K >> 6;

    {
        float* wa_s = (float*)(smem + OFF_WA);
        float* hp_s = (float*)(smem + OFF_HP);
        for (int i = tid; i < NT; i += 512) wa_s[i] = wa[n0 + i];
        int nb = 128 / rpb; if (nb < 1) nb = 1;
        int b0 = m0 / rpb;
        for (int i = tid; i < nb * NT; i += 512)
            hp_s[i] = hproj[(size_t)(b0 + i / NT) * 1024 + n0 + (i % NT)];
    }

    const __half* Abase = A + (size_t)m0 * K;
    const __half* Wbase = W + (size_t)n0 * K;

    float acc[2][NI][4];
    #pragma unroll
    for (int i = 0; i < 2; i++)
        #pragma unroll
        for (int j = 0; j < NI; j++)
            #pragma unroll
            for (int q = 0; q < 4; q++) acc[i][j][q] = 0.f;

    const int lrow = lane & 15;
    const int lhi  = lane >> 4;
    uint32_t a_off[2], b_off[NI / 2];
    #pragma unroll
    for (int mi = 0; mi < 2; mi++)
        a_off[mi] = tile_off(warp_m * 32 + mi * 16 + lrow, lhi);
    #pragma unroll
    for (int p = 0; p < NI / 2; p++)
        b_off[p] = 16384u + tile_off(warp_n * WN + p * 16 + lrow, lhi);

    load_stage<NT>(sb + 0 * STAGE, Abase +   0, Wbase +   0, K, tid); CP_COMMIT();
    load_stage<NT>(sb + 1 * STAGE, Abase +  64, Wbase +  64, K, tid); CP_COMMIT();
    load_stage<NT>(sb + 2 * STAGE, Abase + 128, Wbase + 128, K, tid); CP_COMMIT();

    for (int kc = 0; kc < S; kc++) {
        if (kc + 3 < S)
            load_stage<NT>(sb + ((kc + 3) & 3) * STAGE,
                           Abase + (kc + 3) * 64, Wbase + (kc + 3) * 64, K, tid);
        CP_COMMIT();
        asm volatile("cp.async.wait_group 3;" ::: "memory");
        __syncthreads();
        const uint32_t stage_base = sb + (kc & 3) * STAGE;
        GEMM_CHUNK(NI, stage_base)
    }

    const float* wa_s = (const float*)(smem + OFF_WA);
    const float* hp_s = (const float*)(smem + OFF_HP);
    const int g = lane >> 2, tig = lane & 3;

    #pragma unroll
    for (int mi = 0; mi < 2; mi++) {
        int r0 = warp_m * 32 + mi * 16 + g;
        int r1 = r0 + 8;
        int bl0 = r0 / rpb, bl1 = r1 / rpb;
        const float* hp0 = hp_s + bl0 * NT;
        const float* hp1 = hp_s + bl1 * NT;
        float s0 = 0.f, s1 = 0.f;
        #pragma unroll
        for (int ni = 0; ni < NI; ni++) {
            int cl = warp_n * WN + ni * 8 + 2 * tig;
            float w0 = wa_s[cl], w1 = wa_s[cl + 1];
            float t;
            asm("tanh.approx.f32 %0, %1;" : "=f"(t) : "f"(acc[mi][ni][0] + hp0[cl]));     s0 += t * w0;
            asm("tanh.approx.f32 %0, %1;" : "=f"(t) : "f"(acc[mi][ni][1] + hp0[cl + 1])); s0 += t * w1;
            asm("tanh.approx.f32 %0, %1;" : "=f"(t) : "f"(acc[mi][ni][2] + hp1[cl]));     s1 += t * w0;
            asm("tanh.approx.f32 %0, %1;" : "=f"(t) : "f"(acc[mi][ni][3] + hp1[cl + 1])); s1 += t * w1;
        }
        s0 += __shfl_xor_sync(0xffffffffu, s0, 1);
        s0 += __shfl_xor_sync(0xffffffffu, s0, 2);
        s1 += __shfl_xor_sync(0xffffffffu, s1, 1);
        s1 += __shfl_xor_sync(0xffffffffu, s1, 2);
        if (tig == 0) {
            atomicAdd(&score[m0 + r0], s0);
            atomicAdd(&score[m0 + r1], s1);
        }
    }
}

// ================= GEMM + bias store (hproj) =================
__global__ __launch_bounds__(512, 1) void gemm_bias_mma(
    const __half* __restrict__ A,
    const __half* __restrict__ Ws, const float* __restrict__ bh_s,
    const float* __restrict__ bv_s, float* __restrict__ out_s,
    const __half* __restrict__ Wt, const float* __restrict__ bh_t,
    const float* __restrict__ bv_t, float* __restrict__ out_t)
{
    constexpr int NT = 256, WN = 64, NI = 8, K = HIDDEN;
    constexpr int STAGE = 16384 + NT * 128;
    constexpr int OFF_B = 4 * STAGE;

    extern __shared__ char smem[];
    const uint32_t sb = smem_u32(smem);
    const int tid = threadIdx.x;
    const int lane = tid & 31;
    const int warp = tid >> 5;
    const int warp_m = warp >> 2;
    const int warp_n = warp & 3;
    const int mat = blockIdx.y >> 2;
    const int n0 = (blockIdx.y & 3) * NT;
    const __half* W = mat ? Wt : Ws;
    const float* bh = mat ? bh_t : bh_s;
    const float* bv = mat ? bv_t : bv_s;
    float* out = mat ? out_t : out_s;

    {
        float* b_s = (float*)(smem + OFF_B);
        for (int i = tid; i < NT; i += 512) b_s[i] = bh[n0 + i] + bv[n0 + i];
    }

    const __half* Abase = A;
    const __half* Wbase = W + (size_t)n0 * K;

    float acc[2][NI][4];
    #pragma unroll
    for (int i = 0; i < 2; i++)
        #pragma unroll
        for (int j = 0; j < NI; j++)
            #pragma unroll
            for (int q = 0; q < 4; q++) acc[i][j][q] = 0.f;

    const int lrow = lane & 15;
    const int lhi  = lane >> 4;
    uint32_t a_off[2], b_off[NI / 2];
    #pragma unroll
    for (int mi = 0; mi < 2; mi++)
        a_off[mi] = tile_off(warp_m * 32 + mi * 16 + lrow, lhi);
    #pragma unroll
    for (int p = 0; p < NI / 2; p++)
        b_off[p] = 16384u + tile_off(warp_n * WN + p * 16 + lrow, lhi);

    load_stage<NT>(sb + 0 * STAGE, Abase +   0, Wbase +   0, K, tid); CP_COMMIT();
    load_stage<NT>(sb + 1 * STAGE, Abase +  64, Wbase +  64, K, tid); CP_COMMIT();
    load_stage<NT>(sb + 2 * STAGE, Abase + 128, Wbase + 128, K, tid); CP_COMMIT();

    for (int kc = 0; kc < (K >> 6); kc++) {
        if (kc + 3 < (K >> 6))
            load_stage<NT>(sb + ((kc + 3) & 3) * STAGE,
                           Abase + (kc + 3) * 64, Wbase + (kc + 3) * 64, K, tid);
        CP_COMMIT();
        asm volatile("cp.async.wait_group 3;" ::: "memory");
        __syncthreads();
        const uint32_t stage_base = sb + (kc & 3) * STAGE;
        GEMM_CHUNK(NI, stage_base)
    }

    const float* b_s = (const float*)(smem + OFF_B);
    const int g = lane >> 2, tig = lane & 3;
    #pragma unroll
    for (int mi = 0; mi < 2; mi++) {
        int r0 = warp_m * 32 + mi * 16 + g;
        int r1 = r0 + 8;
        #pragma unroll
        for (int ni = 0; ni < NI; ni++) {
            int cl = warp_n * WN + ni * 8 + 2 * tig;
            if (r0 < 64) {
                out[r0 * 1024 + n0 + cl]     = acc[mi][ni][0] + b_s[cl];
                out[r0 * 1024 + n0 + cl + 1] = acc[mi][ni][1] + b_s[cl + 1];
            }
            if (r1 < 64) {
                out[r1 * 1024 + n0 + cl]     = acc[mi][ni][2] + b_s[cl];
                out[r1 * 1024 + n0 + cl + 1] = acc[mi][ni][3] + b_s[cl + 1];
            }
        }
    }
}

// ================= small kernels =================
__global__ void zero_kernel(float* __restrict__ p, int n) {
    int i = blockIdx.x * blockDim.x + threadIdx.x;
    if (i < n) p[i] = 0.0f;
}

// f32 -> f16, 8 elements per thread (2x LDG.128 + 1x STG.128), n % 8 == 0
__global__ __launch_bounds__(256) void cvt_f2h8(const float* __restrict__ in,
                                                __half* __restrict__ out, int n) {
    int i = (blockIdx.x * blockDim.x + threadIdx.x) * 8;
    if (i < n) {
        float4 v0 = *(const float4*)(in + i);
        float4 v1 = *(const float4*)(in + i + 4);
        uint4 o;
        o.x = h2_bits(__floats2half2_rn(v0.x, v0.y));
        o.y = h2_bits(__floats2half2_rn(v0.z, v0.w));
        o.z = h2_bits(__floats2half2_rn(v1.x, v1.y));
        o.w = h2_bits(__floats2half2_rn(v1.z, v1.w));
        *(uint4*)(out + i) = o;
    }
}

// hidden [64,1024] f32 -> [128,1024] f16 (rows 64..127 zero)
__global__ __launch_bounds__(256) void cvt_hid_pad(const float* __restrict__ in,
                                                   __half* __restrict__ out) {
    int i = (blockIdx.x * blockDim.x + threadIdx.x) * 4;
    if (i < 128 * HIDDEN) {
        __half2* o = (__half2*)(out + i);
        if (i < 64 * HIDDEN) {
            float4 v = *(const float4*)(in + i);
            o[0] = __floats2half2_rn(v.x, v.y);
            o[1] = __floats2half2_rn(v.z, v.w);
        } else {
            o[0] = __floats2half2_rn(0.f, 0.f);
            o[1] = __floats2half2_rn(0.f, 0.f);
        }
    }
}

// spatial softmax + weighted object sum (fp16 uint4 reads) + concat
__global__ __launch_bounds__(256) void spatial_kernel(
    const __half* __restrict__ obj_h, const float* __restrict__ frame,
    const float* __restrict__ score, float* __restrict__ feat,
    __half* __restrict__ feat_h)
{
    int bf = blockIdx.x;
    __shared__ float alpha[NN];
    if (threadIdx.x == 0) {
        float s[NN];
        float mx = -1e30f;
        #pragma unroll
        for (int n = 0; n < NN; n++) { s[n] = score[bf * NN + n]; mx = fmaxf(mx, s[n]); }
        float sum = 0.f;
        #pragma unroll
        for (int n = 0; n < NN; n++) { float e = expf(s[n] - mx); alpha[n] = e; sum += e; }
        float inv = 1.f / sum;
        #pragma unroll
        for (int n = 0; n < NN; n++) alpha[n] *= inv;
    }
    __syncthreads();

    const uint4* base4 = (const uint4*)(obj_h + (size_t)bf * NN * REGION);
    float* frow = feat + (size_t)bf * FEAT2;
    uint4* hrow4 = (uint4*)(feat_h + (size_t)bf * FEAT2);
    for (int d8 = threadIdx.x; d8 < REGION / 8; d8 += 256) {
        float a[8] = {0, 0, 0, 0, 0, 0, 0, 0};
        #pragma unroll 4
        for (int n = 0; n < NN; n++) {
            uint4 v = base4[n * (REGION / 8) + d8];
            float al = alpha[n];
            float2 p0 = __half22float2(*(__half2*)&v.x);
            float2 p1 = __half22float2(*(__half2*)&v.y);
            float2 p2 = __half22float2(*(__half2*)&v.z);
            float2 p3 = __half22float2(*(__half2*)&v.w);
            a[0] += al * p0.x; a[1] += al * p0.y;
            a[2] += al * p1.x; a[3] += al * p1.y;
            a[4] += al * p2.x; a[5] += al * p2.y;
            a[6] += al * p3.x; a[7] += al * p3.y;
        }
        #pragma unroll
        for (int q = 0; q < 8; q++) frow[d8 * 8 + q] = a[q];
        uint4 o;
        o.x = h2_bits(__floats2half2_rn(a[0], a[1]));
        o.y = h2_bits(__floats2half2_rn(a[2], a[3]));
        o.z = h2_bits(__floats2half2_rn(a[4], a[5]));
        o.w = h2_bits(__floats2half2_rn(a[6], a[7]));
        hrow4[d8] = o;
    }
    const float* frm = frame + (size_t)bf * (2 * HIDDEN);
    for (int d = threadIdx.x; d < 2 * HIDDEN; d += 256) {
        float v = frm[d];
        frow[REGION + d] = v;
        feat_h[(size_t)bf * FEAT2 + REGION + d] = __float2half_rn(v);
    }
}

__global__ __launch_bounds__(256) void temporal_kernel(
    const float* __restrict__ feat, const float* __restrict__ score2,
    float* __restrict__ out)
{
    int b = blockIdx.x;
    __shared__ float beta[FF];
    if (threadIdx.x == 0) {
        float s[FF];
        float mx = -1e30f;
        #pragma unroll
        for (int f = 0; f < FF; f++) { s[f] = score2[b * FF + f]; mx = fmaxf(mx, s[f]); }
        float sum = 0.f;
        #pragma unroll
        for (int f = 0; f < FF; f++) { float e = expf(s[f] - mx); beta[f] = e; sum += e; }
        float inv = 1.f / sum;
        #pragma unroll
        for (int f = 0; f < FF; f++) beta[f] *= inv;
    }
    __syncthreads();

    int d0 = blockIdx.y * (FEAT2 / 4);
    for (int d = d0 + threadIdx.x; d < d0 + FEAT2 / 4; d += 256) {
        float acc = 0.f;
        #pragma unroll 8
        for (int f = 0; f < FF; f++)
            acc += beta[f] * feat[((size_t)b * FF + f) * FEAT2 + d];
        out[(size_t)b * FEAT2 + d] = acc;
    }
}

// ================= launch =================
extern "C" void kernel_launch(void* const* d_in, const int* in_sizes, int n_in,
                              void* d_out, int out_size)
{
    const float* frame  = (const float*)d_in[0];
    const float* obj    = (const float*)d_in[1];
    const float* hidden = (const float*)d_in[2];
    const float* s_wh_w = (const float*)d_in[3];
    const float* s_wh_b = (const float*)d_in[4];
    const float* s_wv_w = (const float*)d_in[5];
    const float* s_wv_b = (const float*)d_in[6];
    const float* s_wa_w = (const float*)d_in[7];
    const float* t_wh_w = (const float*)d_in[8];
    const float* t_wh_b = (const float*)d_in[9];
    const float* t_wv_w = (const float*)d_in[10];
    const float* t_wv_b = (const float*)d_in[11];
    const float* t_wa_w = (const float*)d_in[12];
    float* out = (float*)d_out;

    float *p_hs, *p_ht, *p_s1, *p_feat, *p_s2;
    __half *p_obj_h, *p_feat_h, *p_swv_h, *p_twv_h, *p_swh_h, *p_twh_h, *p_hid_h;
    cudaGetSymbolAddress((void**)&p_hs, g_hproj_s);
    cudaGetSymbolAddress((void**)&p_ht, g_hproj_t);
    cudaGetSymbolAddress((void**)&p_s1, g_score1);
    cudaGetSymbolAddress((void**)&p_feat, g_feat);
    cudaGetSymbolAddress((void**)&p_s2, g_score2);
    cudaGetSymbolAddress((void**)&p_obj_h, g_obj_h);
    cudaGetSymbolAddress((void**)&p_feat_h, g_feat_h);
    cudaGetSymbolAddress((void**)&p_swv_h, g_swv_h);
    cudaGetSymbolAddress((void**)&p_twv_h, g_twv_h);
    cudaGetSymbolAddress((void**)&p_swh_h, g_swh_h);
    cudaGetSymbolAddress((void**)&p_twh_h, g_twh_h);
    cudaGetSymbolAddress((void**)&p_hid_h, g_hid_h);

    const int SMEM_PERS = 4 * (16384 + 256 * 128) + 256 * 4 + 4 * 256 * 4 + 4 * 128 * 4; // 203776
    const int SMEM_128  = 4 * (16384 + 128 * 128) + 128 * 4 + 4 * 128 * 4;               // 133632
    const int SMEM_B    = 4 * (16384 + 256 * 128) + 256 * 4;                             // 197632
    cudaFuncSetAttribute(gemm_score_pers<256, 4>, cudaFuncAttributeMaxDynamicSharedMemorySize, SMEM_PERS);
    cudaFuncSetAttribute(gemm_score_mma<128>, cudaFuncAttributeMaxDynamicSharedMemorySize, SMEM_128);
    cudaFuncSetAttribute(gemm_bias_mma, cudaFuncAttributeMaxDynamicSharedMemorySize, SMEM_B);

    // fp16 conversions (8 elems/thread)
    {
        int n_swh = 1024 * HIDDEN;
        cvt_f2h8<<<(n_swh / 8 + 255) / 256, 256>>>(s_wh_w, p_swh_h, n_swh);
        cvt_f2h8<<<(n_swh / 8 + 255) / 256, 256>>>(t_wh_w, p_twh_h, n_swh);
        cvt_hid_pad<<<(128 * HIDDEN / 4 + 255) / 256, 256>>>(hidden, p_hid_h);
        int n_swv = 1024 * REGION;
        cvt_f2h8<<<(n_swv / 8 + 255) / 256, 256>>>(s_wv_w, p_swv_h, n_swv);
        int n_twv = 1024 * FEAT2;
        cvt_f2h8<<<(n_twv / 8 + 255) / 256, 256>>>(t_wv_w, p_twv_h, n_twv);
        int n_obj = M1 * REGION;
        cvt_f2h8<<<(n_obj / 8 + 255) / 256, 256>>>(obj, p_obj_h, n_obj);
    }

    // hidden-state projections as one mma GEMM launch (both matrices)
    gemm_bias_mma<<<dim3(1, 8), 512, SMEM_B>>>(p_hid_h,
                                               p_swh_h, s_wh_b, s_wv_b, p_hs,
                                               p_twh_h, t_wh_b, t_wv_b, p_ht);

    // spatial attention scores: persistent GEMM, 144 CTAs x 4 m-blocks x 4 n-tiles
    gemm_score_pers<256, 4><<<144, 512, SMEM_PERS>>>(
        p_obj_h, p_swv_h, p_hs, s_wa_w, p_s1, REGION, FF * NN, (M1 / 128) / 144);

    // softmax over boxes + weighted object sum (fp16 obj) + concat frame feats
    spatial_kernel<<<M2, 256>>>(p_obj_h, frame, p_s1, p_feat, p_feat_h);

    // temporal attention scores (legacy kernel, atomics)
    zero_kernel<<<(M2 + 255) / 256, 256>>>(p_s2, M2);
    gemm_score_mma<128><<<dim3(8, M2 / 128), 512, SMEM_128>>>(
        p_feat_h, p_twv_h, p_ht, t_wa_w, p_s2, FEAT2, FF);

    // softmax over frames + weighted feat sum -> [64, 3072]
    temporal_kernel<<<dim3(BB, 4), 256>>>(p_feat, p_s2, out);
}